// round 1
// baseline (speedup 1.0000x reference)
#include <cuda_runtime.h>
#include <math.h>

// Shapes
#define BATCH 64
#define C1    64
#define C2    128
#define H0    224
#define W0    224
#define H1    112
#define W1    112
#define H2    56
#define W2    56

// Scratch: conv1 output for both experts (relu'd), 2*64*64*112*112 floats = 411MB
__device__ float g_h1[(size_t)2 * BATCH * C1 * H1 * W1];
// Partial pool sums: [expert][b][oc][row_tile(7)]
__device__ float g_pool[2 * BATCH * C2 * 7];

// ---------------------------------------------------------------------------
// Kernel 1: conv1 3x3 stride2 SAME (pad lo=0, hi=1) + bias + ReLU
// grid(7 row-tiles, 64 batch, 2 experts), block 224
// Each block: 16 output rows x 112 cols x 64 oc for one image.
// Thread slot = (oh_local, ow group of 4); 4 passes over 16-oc slabs.
// ---------------------------------------------------------------------------
__global__ __launch_bounds__(224) void conv1_kernel(
    const float* __restrict__ x,
    const float* __restrict__ tw1, const float* __restrict__ tb1,
    const float* __restrict__ fw1, const float* __restrict__ fb1)
{
    extern __shared__ float smem[];
    float* sin = smem;                 // [3][33][226]
    float* sw  = smem + 3 * 33 * 226;  // [27][64]

    const int rt  = blockIdx.x;   // 0..6 (16 output rows each)
    const int b   = blockIdx.y;
    const int e   = blockIdx.z;
    const float* w1 = e ? fw1 : tw1;
    const float* b1 = e ? fb1 : tb1;
    const int tid = threadIdx.x;

    // weights: w1[oc][ic][dy][dx] -> sw[k*64 + oc], k = ic*9+dy*3+dx
    for (int i = tid; i < 27 * 64; i += 224) {
        int k = i >> 6, oc = i & 63;
        sw[i] = w1[oc * 27 + k];
    }

    // input rows r0..r0+32 (33), cols 0..224 (225, col 224 = pad), 3 channels
    const int r0 = rt * 32;
    const float* xb = x + (size_t)b * 3 * H0 * W0;
    for (int i = tid; i < 3 * 33 * 225; i += 224) {
        int c  = i % 225;
        int t2 = i / 225;
        int r  = t2 % 33;
        int ic = t2 / 33;
        int gr = r0 + r;
        float v = 0.f;
        if (gr < H0 && c < W0) v = xb[(size_t)ic * H0 * W0 + (size_t)gr * W0 + c];
        sin[(ic * 33 + r) * 226 + c] = v;
    }
    __syncthreads();

    float* out_base = g_h1 + ((size_t)e * BATCH + b) * C1 * H1 * W1;

    for (int s = tid; s < 448; s += 224) {
        const int ohl = s / 28;
        const int ow0 = (s % 28) * 4;
        const int oh  = rt * 16 + ohl;

        for (int pass = 0; pass < 4; ++pass) {
            float4 acc[16];
            #pragma unroll
            for (int o = 0; o < 16; ++o) {
                float bb = b1[pass * 16 + o];
                acc[o] = make_float4(bb, bb, bb, bb);
            }
            #pragma unroll
            for (int ic = 0; ic < 3; ++ic) {
                float iv[3][9];
                #pragma unroll
                for (int dy = 0; dy < 3; ++dy)
                    #pragma unroll
                    for (int c = 0; c < 9; ++c)
                        iv[dy][c] = sin[(ic * 33 + 2 * ohl + dy) * 226 + 2 * ow0 + c];
                #pragma unroll
                for (int dy = 0; dy < 3; ++dy)
                    #pragma unroll
                    for (int dx = 0; dx < 3; ++dx) {
                        float v0 = iv[dy][dx],     v1 = iv[dy][2 + dx];
                        float v2 = iv[dy][4 + dx], v3 = iv[dy][6 + dx];
                        const float* wr = &sw[(ic * 9 + dy * 3 + dx) * 64 + pass * 16];
                        #pragma unroll
                        for (int o = 0; o < 16; ++o) {
                            float w = wr[o];
                            acc[o].x += v0 * w; acc[o].y += v1 * w;
                            acc[o].z += v2 * w; acc[o].w += v3 * w;
                        }
                    }
            }
            #pragma unroll
            for (int o = 0; o < 16; ++o) {
                int oc = pass * 16 + o;
                float4 r;
                r.x = fmaxf(acc[o].x, 0.f); r.y = fmaxf(acc[o].y, 0.f);
                r.z = fmaxf(acc[o].z, 0.f); r.w = fmaxf(acc[o].w, 0.f);
                *(float4*)(out_base + (size_t)oc * H1 * W1 + (size_t)oh * W1 + ow0) = r;
            }
        }
    }
}

// ---------------------------------------------------------------------------
// Kernel 2: conv2 3x3 stride2 SAME + bias + ReLU + spatial-sum (pool partial)
// grid(7 row-tiles, 4 oc-groups, 128 = expert*64+b), block 224
// Thread: (ow, oh pair) computes 2 output rows x 32 oc accumulators.
// 8-ic smem chunks; deterministic block reduction into g_pool partials.
// ---------------------------------------------------------------------------
#define ICK 8
__global__ __launch_bounds__(224) void conv2_kernel(
    const float* __restrict__ tw2, const float* __restrict__ tb2,
    const float* __restrict__ fw2, const float* __restrict__ fb2)
{
    extern __shared__ float smem[];
    float* sin  = smem;                        // [8][17][114] = 15504
    float* sw   = smem + ICK * 17 * 114;       // [8][9][32]   = 2304
    float* sred = sw + ICK * 9 * 32;           // [7][32]

    const int rt  = blockIdx.x;      // 0..6, 8 output rows each
    const int ocg = blockIdx.y;      // 0..3, 32 oc each
    const int eb  = blockIdx.z;
    const int e   = eb >> 6;
    const int b   = eb & 63;
    const float* w2 = e ? fw2 : tw2;
    const float* b2 = e ? fb2 : tb2;

    const int tid = threadIdx.x;
    const int ow  = tid % 56;
    const int ohp = tid / 56;        // 0..3 -> output rows 2*ohp, 2*ohp+1 (local)

    const float* in_base = g_h1 + ((size_t)e * BATCH + b) * C1 * H1 * W1;
    const int r0 = rt * 16;          // input row base (17 rows needed)

    float4 accA[8], accB[8];
    #pragma unroll
    for (int o = 0; o < 8; ++o) {
        int base = ocg * 32 + o * 4;
        float4 bb = make_float4(b2[base], b2[base + 1], b2[base + 2], b2[base + 3]);
        accA[o] = bb;
        accB[o] = bb;
    }

    for (int ic0 = 0; ic0 < C1; ic0 += ICK) {
        __syncthreads();
        // input chunk: [icl][17 rows][113 cols] (row 112 / col 112 = pad 0)
        for (int i = tid; i < ICK * 17 * 113; i += 224) {
            int c   = i % 113;
            int t2  = i / 113;
            int r   = t2 % 17;
            int icl = t2 / 17;
            int gr  = r0 + r;
            float v = 0.f;
            if (gr < H1 && c < W1)
                v = in_base[(size_t)(ic0 + icl) * H1 * W1 + (size_t)gr * W1 + c];
            sin[(icl * 17 + r) * 114 + c] = v;
        }
        // weights: sw[(icl*9+k)*32 + ocl]
        for (int i = tid; i < ICK * 9 * 32; i += 224) {
            int ocl = i & 31;
            int t2  = i >> 5;
            int k   = t2 % 9;
            int icl = t2 / 9;
            sw[i] = w2[(size_t)(ocg * 32 + ocl) * 576 + (size_t)(ic0 + icl) * 9 + k];
        }
        __syncthreads();

        #pragma unroll
        for (int icl = 0; icl < ICK; ++icl) {
            float iv[5][3];
            #pragma unroll
            for (int r = 0; r < 5; ++r)
                #pragma unroll
                for (int c = 0; c < 3; ++c)
                    iv[r][c] = sin[(icl * 17 + 4 * ohp + r) * 114 + 2 * ow + c];
            const float4* w4 = (const float4*)&sw[icl * 9 * 32];
            #pragma unroll
            for (int dy = 0; dy < 3; ++dy)
                #pragma unroll
                for (int dx = 0; dx < 3; ++dx) {
                    float va = iv[dy][dx];
                    float vb = iv[dy + 2][dx];
                    #pragma unroll
                    for (int o = 0; o < 8; ++o) {
                        float4 w = w4[(dy * 3 + dx) * 8 + o];
                        accA[o].x += va * w.x; accA[o].y += va * w.y;
                        accA[o].z += va * w.z; accA[o].w += va * w.w;
                        accB[o].x += vb * w.x; accB[o].y += vb * w.y;
                        accB[o].z += vb * w.z; accB[o].w += vb * w.w;
                    }
                }
        }
    }

    // ReLU + sum the 2 positions, warp-shuffle reduce (deterministic)
    const int lane = tid & 31;
    const int warp = tid >> 5;   // 0..6
    #pragma unroll
    for (int o = 0; o < 8; ++o) {
        float4 s;
        s.x = fmaxf(accA[o].x, 0.f) + fmaxf(accB[o].x, 0.f);
        s.y = fmaxf(accA[o].y, 0.f) + fmaxf(accB[o].y, 0.f);
        s.z = fmaxf(accA[o].z, 0.f) + fmaxf(accB[o].z, 0.f);
        s.w = fmaxf(accA[o].w, 0.f) + fmaxf(accB[o].w, 0.f);
        #pragma unroll
        for (int off = 16; off > 0; off >>= 1) {
            s.x += __shfl_down_sync(0xffffffffu, s.x, off);
            s.y += __shfl_down_sync(0xffffffffu, s.y, off);
            s.z += __shfl_down_sync(0xffffffffu, s.z, off);
            s.w += __shfl_down_sync(0xffffffffu, s.w, off);
        }
        if (lane == 0) {
            sred[warp * 32 + o * 4 + 0] = s.x;
            sred[warp * 32 + o * 4 + 1] = s.y;
            sred[warp * 32 + o * 4 + 2] = s.z;
            sred[warp * 32 + o * 4 + 3] = s.w;
        }
    }
    __syncthreads();
    if (tid < 32) {
        float t = 0.f;
        #pragma unroll
        for (int w = 0; w < 7; ++w) t += sred[w * 32 + tid];
        g_pool[(((size_t)e * BATCH + b) * C2 + ocg * 32 + tid) * 7 + rt] = t;
    }
}

// ---------------------------------------------------------------------------
// Kernel 3: pool mean -> FC -> softmax conf -> threshold blend -> output+freq
// 1 block, 64 threads (1 per batch row)
// ---------------------------------------------------------------------------
__global__ void head_kernel(
    const float* __restrict__ twf, const float* __restrict__ tbf,
    const float* __restrict__ fwf, const float* __restrict__ fbf,
    float* __restrict__ out, int out_size)
{
    __shared__ int scount;
    const int b = threadIdx.x;   // 0..63
    if (b == 0) scount = 0;
    __syncthreads();

    float tl0 = tbf[0], tl1 = tbf[1];
    float fl0 = fbf[0], fl1 = fbf[1];
    const float inv = 1.f / (float)(H2 * W2);
    for (int oc = 0; oc < C2; ++oc) {
        const float* pt = &g_pool[(((size_t)0 * BATCH + b) * C2 + oc) * 7];
        float gt = (pt[0] + pt[1] + pt[2] + pt[3] + pt[4] + pt[5] + pt[6]) * inv;
        tl0 += gt * twf[oc * 2 + 0];
        tl1 += gt * twf[oc * 2 + 1];
        const float* pf = &g_pool[(((size_t)1 * BATCH + b) * C2 + oc) * 7];
        float gf = (pf[0] + pf[1] + pf[2] + pf[3] + pf[4] + pf[5] + pf[6]) * inv;
        fl0 += gf * fwf[oc * 2 + 0];
        fl1 += gf * fwf[oc * 2 + 1];
    }

    // 2-class softmax max prob = 1 / (1 + exp(-|l0 - l1|))
    float conf = 1.f / (1.f + expf(-fabsf(tl0 - tl1)));
    bool use2 = (conf <= 0.9f);
    float o0 = use2 ? (0.7f * tl0 + 0.3f * fl0) : tl0;
    float o1 = use2 ? (0.7f * tl1 + 0.3f * fl1) : tl1;
    out[b * 2 + 0] = o0;
    out[b * 2 + 1] = o1;
    if (use2) atomicAdd(&scount, 1);
    __syncthreads();
    if (b == 0 && out_size > 2 * BATCH)
        out[2 * BATCH] = (float)scount / (float)BATCH;
}

// ---------------------------------------------------------------------------
extern "C" void kernel_launch(void* const* d_in, const int* in_sizes, int n_in,
                              void* d_out, int out_size)
{
    const float* x    = (const float*)d_in[0];
    const float* t_w1 = (const float*)d_in[1];
    const float* t_b1 = (const float*)d_in[2];
    const float* t_w2 = (const float*)d_in[3];
    const float* t_b2 = (const float*)d_in[4];
    const float* t_wf = (const float*)d_in[5];
    const float* t_bf = (const float*)d_in[6];
    const float* f_w1 = (const float*)d_in[7];
    const float* f_b1 = (const float*)d_in[8];
    const float* f_w2 = (const float*)d_in[9];
    const float* f_b2 = (const float*)d_in[10];
    const float* f_wf = (const float*)d_in[11];
    const float* f_bf = (const float*)d_in[12];
    float* out = (float*)d_out;

    const int smem1 = (3 * 33 * 226 + 27 * 64) * 4;                    // 96408 B
    const int smem2 = (ICK * 17 * 114 + ICK * 9 * 32 + 7 * 32) * 4;    // 72128 B
    cudaFuncSetAttribute(conv1_kernel, cudaFuncAttributeMaxDynamicSharedMemorySize, smem1);
    cudaFuncSetAttribute(conv2_kernel, cudaFuncAttributeMaxDynamicSharedMemorySize, smem2);

    dim3 g1(7, BATCH, 2);
    conv1_kernel<<<g1, 224, smem1>>>(x, t_w1, t_b1, f_w1, f_b1);

    dim3 g2(7, 4, 2 * BATCH);
    conv2_kernel<<<g2, 224, smem2>>>(t_w2, t_b2, f_w2, f_b2);

    head_kernel<<<1, BATCH>>>(t_wf, t_bf, f_wf, f_bf, out, out_size);
}

// round 5
// speedup vs baseline: 2.4528x; 2.4528x over previous
#include <cuda_runtime.h>
#include <cuda_bf16.h>
#include <math.h>
#include <stdint.h>

#define BATCH 64
#define C1    64
#define C2    128
#define H0    224
#define W0    224
#define H1    112
#define W1    112
#define PIX   (H1*W1)
#define NT2   28            // conv2 tiles: 2 output rows each (56 rows / 2)

// conv1 output, channel-last packed: [imgexp][h][w][ic] uint32 = (bf16 hi | bf16 mid<<16)
__device__ uint32_t g_h1p[(size_t)2 * BATCH * PIX * C1];
// packed conv2 weights: [e][tap][part(hi,mid)][oc=128][ic=64] bf16
__device__ unsigned short g_w2pack[2 * 9 * 2 * 128 * 64];
// pool partials: [imgexp][oc][tile]
__device__ float g_pool[2 * BATCH * C2 * NT2];

__device__ __forceinline__ uint32_t pack_bf16_split(float v) {
    __nv_bfloat16 h = __float2bfloat16(v);
    float hf = __bfloat162float(h);
    __nv_bfloat16 m = __float2bfloat16(v - hf);
    return (uint32_t)__bfloat16_as_ushort(h) | ((uint32_t)__bfloat16_as_ushort(m) << 16);
}

// mma.sync m16n8k16 bf16 (baseline PTX, works on plain sm_103 target)
#define MMA_BF16(d, a, b) \
    asm volatile("mma.sync.aligned.m16n8k16.row.col.f32.bf16.bf16.f32 " \
        "{%0,%1,%2,%3}, {%4,%5,%6,%7}, {%8,%9}, {%0,%1,%2,%3};" \
        : "+f"((d)[0]), "+f"((d)[1]), "+f"((d)[2]), "+f"((d)[3]) \
        : "r"((a)[0]), "r"((a)[1]), "r"((a)[2]), "r"((a)[3]), \
          "r"((b)[0]), "r"((b)[1]))

// ---------------------------------------------------------------------------
// conv1: 3x3 s2 SAME + bias + ReLU, channel-last packed bf16-split output.
// grid(49 tiles of 16x16, 128 imgexp), block 256, thread = 1 pixel x 64 oc.
// ---------------------------------------------------------------------------
__global__ __launch_bounds__(256) void conv1_kernel(
    const float* __restrict__ x,
    const float* __restrict__ tw1, const float* __restrict__ tb1,
    const float* __restrict__ fw1, const float* __restrict__ fb1)
{
    __shared__ float sin[3][33][36];
    __shared__ float sw[27 * 64];

    const int tile = blockIdx.x;
    const int imgexp = blockIdx.y;
    const int e = imgexp >> 6;
    const int b = imgexp & 63;
    const float* w1 = e ? fw1 : tw1;
    const float* b1 = e ? fb1 : tb1;
    const int tid = threadIdx.x;

    const int ty0 = (tile / 7) * 16;
    const int tx0 = (tile % 7) * 16;

    for (int i = tid; i < 27 * 64; i += 256) {
        int k = i >> 6, oc = i & 63;
        sw[i] = w1[oc * 27 + k];
    }
    const int r0 = 2 * ty0, c0 = 2 * tx0;
    const float* xb = x + (size_t)b * 3 * H0 * W0;
    for (int i = tid; i < 3 * 33 * 33; i += 256) {
        int ic = i / 1089;
        int rem = i - ic * 1089;
        int r = rem / 33, c = rem - (rem / 33) * 33;
        int gr = r0 + r, gc = c0 + c;
        float v = 0.f;
        if (gr < H0 && gc < W0) v = xb[(size_t)ic * H0 * W0 + (size_t)gr * W0 + gc];
        sin[ic][r][c] = v;
    }
    __syncthreads();

    const int ty = tid >> 4, tx = tid & 15;
    float4 acc[16];
    const float4* b4 = (const float4*)b1;
    #pragma unroll
    for (int j = 0; j < 16; ++j) acc[j] = b4[j];

    #pragma unroll
    for (int ic = 0; ic < 3; ++ic) {
        float iv[9];
        #pragma unroll
        for (int dy = 0; dy < 3; ++dy)
            #pragma unroll
            for (int dx = 0; dx < 3; ++dx)
                iv[dy * 3 + dx] = sin[ic][2 * ty + dy][2 * tx + dx];
        #pragma unroll
        for (int k = 0; k < 9; ++k) {
            float v = iv[k];
            const float4* w4 = (const float4*)&sw[(ic * 9 + k) * 64];
            #pragma unroll
            for (int j = 0; j < 16; ++j) {
                float4 w = w4[j];
                acc[j].x += v * w.x; acc[j].y += v * w.y;
                acc[j].z += v * w.z; acc[j].w += v * w.w;
            }
        }
    }

    const int oh = ty0 + ty, ow = tx0 + tx;
    uint4* dst = (uint4*)(g_h1p + (size_t)imgexp * PIX * C1 + (size_t)(oh * W1 + ow) * C1);
    #pragma unroll
    for (int j = 0; j < 16; ++j) {
        uint4 o;
        o.x = pack_bf16_split(fmaxf(acc[j].x, 0.f));
        o.y = pack_bf16_split(fmaxf(acc[j].y, 0.f));
        o.z = pack_bf16_split(fmaxf(acc[j].z, 0.f));
        o.w = pack_bf16_split(fmaxf(acc[j].w, 0.f));
        dst[j] = o;
    }
}

// ---------------------------------------------------------------------------
// weight pack: w2[oc][ic][3][3] fp32 -> g_w2pack[e][tap][part][oc][ic] bf16
// ---------------------------------------------------------------------------
__global__ void pack_w2_kernel(const float* __restrict__ tw2, const float* __restrict__ fw2)
{
    int idx = blockIdx.x * blockDim.x + threadIdx.x;
    if (idx >= 2 * 9 * 128 * 64) return;
    int e   = idx / 73728;
    int rem = idx - e * 73728;
    int tap = rem / 8192;
    int rem2 = rem - tap * 8192;
    int oc = rem2 >> 6, ic = rem2 & 63;
    float w = (e ? fw2 : tw2)[oc * 576 + ic * 9 + tap];
    __nv_bfloat16 h = __float2bfloat16(w);
    float hf = __bfloat162float(h);
    __nv_bfloat16 m = __float2bfloat16(w - hf);
    size_t base = (((size_t)(e * 9 + tap) * 2) * 128 + oc) * 64 + ic;
    g_w2pack[base]            = __bfloat16_as_ushort(h);
    g_w2pack[base + 128 * 64] = __bfloat16_as_ushort(m);
}

// ---------------------------------------------------------------------------
// conv2 via mma.sync (HMMA): CTA = (imgexp, 2-output-row tile): M=128 x N=112
// 8 warps (4 M x 2 N), warp tile 32 x 56, bf16-split 3-combo accumulation.
// smem: A [buf2][part2][128 rows x 144B], B [buf2][part2][112 rows x 144B], sred
// ---------------------------------------------------------------------------
#define A_BUF_BYTES   36864      // 2 parts * 128 * 144
#define B_OFF2        73728      // 2 A buffers
#define B_BUF_BYTES   32256      // 2 parts * 112 * 144
#define SRED_OFF      (B_OFF2 + 2 * B_BUF_BYTES)   // 138240
#define SMEM2_BYTES   (SRED_OFF + 128 * 2 * 4)     // 139264

__global__ __launch_bounds__(256) void conv2_mma_kernel(
    const float* __restrict__ tb2, const float* __restrict__ fb2)
{
    extern __shared__ char smem[];
    const int tid = threadIdx.x;
    const int wid = tid >> 5, lane = tid & 31;
    const int wm = wid & 3;          // M warp: 32*wm
    const int wn = wid >> 2;         // N warp: 56*wn
    const int tileIdx = blockIdx.x;  // 0..27
    const int imgexp  = blockIdx.y;  // 0..127
    const int e = imgexp >> 6;
    const int oh0 = tileIdx * 2;

    const uint4* wsrc = (const uint4*)g_w2pack + (size_t)e * 9 * 2048;
    const uint4* src  = (const uint4*)g_h1p + (size_t)imgexp * PIX * 16;

    float acc[2][7][4];
    #pragma unroll
    for (int mt = 0; mt < 2; ++mt)
        #pragma unroll
        for (int nt = 0; nt < 7; ++nt)
            #pragma unroll
            for (int j = 0; j < 4; ++j) acc[mt][nt][j] = 0.f;

    // ---- staging lambdas ----
    auto stageA = [&](int t, int buf) {
        const uint4* ws = wsrc + t * 2048;
        char* ab = smem + buf * A_BUF_BYTES;
        #pragma unroll
        for (int ii = 0; ii < 8; ++ii) {
            int i = tid + ii * 256;              // 0..2047
            int part = i >> 10, idx = i & 1023;
            int row = idx >> 3, col = idx & 7;
            *(uint4*)(ab + part * 18432 + row * 144 + col * 16) = ws[i];
        }
    };
    auto stageB = [&](int t, int buf) {
        const int dy = t / 3, dx = t - (t / 3) * 3;
        char* bb = smem + B_OFF2 + buf * B_BUF_BYTES;
        #pragma unroll
        for (int ii = 0; ii < 7; ++ii) {
            int i = tid + ii * 256;              // 0..1791
            int n = i >> 4, icq = i & 15;
            int ohl = (n >= 56) ? 1 : 0;
            int ow = n - ohl * 56;
            int ih = 2 * (oh0 + ohl) + dy;
            int iw = 2 * ow + dx;
            uint4 v = make_uint4(0u, 0u, 0u, 0u);
            if (ih < H1 && iw < W1) v = src[(ih * W1 + iw) * 16 + icq];
            uint32_t off = (uint32_t)(n * 144 + icq * 8);
            uint2 h, m;
            h.x = (v.x & 0xffffu) | (v.y << 16);
            h.y = (v.z & 0xffffu) | (v.w << 16);
            m.x = (v.x >> 16) | (v.y & 0xffff0000u);
            m.y = (v.z >> 16) | (v.w & 0xffff0000u);
            *(uint2*)(bb + off) = h;
            *(uint2*)(bb + 16128 + off) = m;
        }
    };

    stageA(0, 0); stageB(0, 0);
    __syncthreads();

    const int mrow = lane >> 2;
    const int koff = (lane & 3) * 4;

    for (int t = 0; t < 9; ++t) {
        const int buf = t & 1;
        if (t < 8) { stageA(t + 1, (t + 1) & 1); stageB(t + 1, (t + 1) & 1); }

        const char* ab = smem + buf * A_BUF_BYTES;
        const char* bb = smem + B_OFF2 + buf * B_BUF_BYTES;
        const char* aptr = ab + (wm * 32 + mrow) * 144 + koff;
        const char* bptr = bb + (wn * 56 + mrow) * 144 + koff;

        #pragma unroll
        for (int kk = 0; kk < 4; ++kk) {
            uint32_t Ah[2][4], Am[2][4];
            #pragma unroll
            for (int mt = 0; mt < 2; ++mt) {
                const char* p = aptr + mt * (16 * 144) + kk * 32;
                Ah[mt][0] = *(const uint32_t*)(p);
                Ah[mt][1] = *(const uint32_t*)(p + 8 * 144);
                Ah[mt][2] = *(const uint32_t*)(p + 16);
                Ah[mt][3] = *(const uint32_t*)(p + 8 * 144 + 16);
                const char* q = p + 18432;
                Am[mt][0] = *(const uint32_t*)(q);
                Am[mt][1] = *(const uint32_t*)(q + 8 * 144);
                Am[mt][2] = *(const uint32_t*)(q + 16);
                Am[mt][3] = *(const uint32_t*)(q + 8 * 144 + 16);
            }
            uint32_t Bh[7][2], Bm[7][2];
            #pragma unroll
            for (int nt = 0; nt < 7; ++nt) {
                const char* p = bptr + nt * (8 * 144) + kk * 32;
                Bh[nt][0] = *(const uint32_t*)(p);
                Bh[nt][1] = *(const uint32_t*)(p + 16);
                const char* q = p + 16128;
                Bm[nt][0] = *(const uint32_t*)(q);
                Bm[nt][1] = *(const uint32_t*)(q + 16);
            }
            #pragma unroll
            for (int mt = 0; mt < 2; ++mt)
                #pragma unroll
                for (int nt = 0; nt < 7; ++nt) {
                    MMA_BF16(acc[mt][nt], Ah[mt], Bh[nt]);
                    MMA_BF16(acc[mt][nt], Ah[mt], Bm[nt]);
                    MMA_BF16(acc[mt][nt], Am[mt], Bh[nt]);
                }
        }
        __syncthreads();
    }

    // epilogue: bias + relu per element, deterministic pooled partial per oc
    float* sred = (float*)(smem + SRED_OFF);
    const float* b2 = e ? fb2 : tb2;
    #pragma unroll
    for (int mt = 0; mt < 2; ++mt) {
        int m0 = wm * 32 + mt * 16 + mrow;
        float bias0 = b2[m0], bias1 = b2[m0 + 8];
        float s0 = 0.f, s1 = 0.f;
        #pragma unroll
        for (int nt = 0; nt < 7; ++nt) {
            s0 += fmaxf(acc[mt][nt][0] + bias0, 0.f) + fmaxf(acc[mt][nt][1] + bias0, 0.f);
            s1 += fmaxf(acc[mt][nt][2] + bias1, 0.f) + fmaxf(acc[mt][nt][3] + bias1, 0.f);
        }
        s0 += __shfl_xor_sync(0xffffffffu, s0, 1);
        s0 += __shfl_xor_sync(0xffffffffu, s0, 2);
        s1 += __shfl_xor_sync(0xffffffffu, s1, 1);
        s1 += __shfl_xor_sync(0xffffffffu, s1, 2);
        if ((lane & 3) == 0) {
            sred[m0 * 2 + wn] = s0;
            sred[(m0 + 8) * 2 + wn] = s1;
        }
    }
    __syncthreads();
    if (tid < 128)
        g_pool[((size_t)imgexp * C2 + tid) * NT2 + tileIdx] = sred[tid * 2] + sred[tid * 2 + 1];
}

// ---------------------------------------------------------------------------
// head: pool mean -> FC -> conf -> blend -> out + freq
// ---------------------------------------------------------------------------
__global__ void head_kernel(
    const float* __restrict__ twf, const float* __restrict__ tbf,
    const float* __restrict__ fwf, const float* __restrict__ fbf,
    float* __restrict__ out, int out_size)
{
    __shared__ int scount;
    const int b = threadIdx.x;
    if (b == 0) scount = 0;
    __syncthreads();

    float tl0 = tbf[0], tl1 = tbf[1];
    float fl0 = fbf[0], fl1 = fbf[1];
    const float inv = 1.f / 3136.f;
    for (int oc = 0; oc < C2; ++oc) {
        const float* pt = &g_pool[((size_t)b * C2 + oc) * NT2];
        float gt = 0.f;
        #pragma unroll
        for (int k = 0; k < NT2; ++k) gt += pt[k];
        gt *= inv;
        tl0 += gt * twf[oc * 2 + 0];
        tl1 += gt * twf[oc * 2 + 1];
        const float* pf = &g_pool[((size_t)(BATCH + b) * C2 + oc) * NT2];
        float gf = 0.f;
        #pragma unroll
        for (int k = 0; k < NT2; ++k) gf += pf[k];
        gf *= inv;
        fl0 += gf * fwf[oc * 2 + 0];
        fl1 += gf * fwf[oc * 2 + 1];
    }

    float conf = 1.f / (1.f + expf(-fabsf(tl0 - tl1)));
    bool use2 = (conf <= 0.9f);
    out[b * 2 + 0] = use2 ? (0.7f * tl0 + 0.3f * fl0) : tl0;
    out[b * 2 + 1] = use2 ? (0.7f * tl1 + 0.3f * fl1) : tl1;
    if (use2) atomicAdd(&scount, 1);
    __syncthreads();
    if (b == 0 && out_size > 2 * BATCH)
        out[2 * BATCH] = (float)scount / (float)BATCH;
}

// ---------------------------------------------------------------------------
extern "C" void kernel_launch(void* const* d_in, const int* in_sizes, int n_in,
                              void* d_out, int out_size)
{
    const float* x    = (const float*)d_in[0];
    const float* t_w1 = (const float*)d_in[1];
    const float* t_b1 = (const float*)d_in[2];
    const float* t_w2 = (const float*)d_in[3];
    const float* t_b2 = (const float*)d_in[4];
    const float* t_wf = (const float*)d_in[5];
    const float* t_bf = (const float*)d_in[6];
    const float* f_w1 = (const float*)d_in[7];
    const float* f_b1 = (const float*)d_in[8];
    const float* f_w2 = (const float*)d_in[9];
    const float* f_b2 = (const float*)d_in[10];
    const float* f_wf = (const float*)d_in[11];
    const float* f_bf = (const float*)d_in[12];
    float* out = (float*)d_out;

    cudaFuncSetAttribute(conv2_mma_kernel, cudaFuncAttributeMaxDynamicSharedMemorySize, SMEM2_BYTES);

    pack_w2_kernel<<<144, 1024>>>(t_w2, f_w2);

    dim3 g1(49, 2 * BATCH);
    conv1_kernel<<<g1, 256>>>(x, t_w1, t_b1, f_w1, f_b1);

    dim3 g2(NT2, 2 * BATCH);
    conv2_mma_kernel<<<g2, 256, SMEM2_BYTES>>>(t_b2, f_b2);

    head_kernel<<<1, BATCH>>>(t_wf, t_bf, f_wf, f_bf, out, out_size);
}

// round 7
// speedup vs baseline: 3.5935x; 1.4651x over previous
#include <cuda_runtime.h>
#include <cuda_bf16.h>
#include <math.h>
#include <stdint.h>

#define BATCH 64
#define C1    64
#define C2    128
#define H0    224
#define W0    224
#define H1    112
#define W1    112
#define PIX   (H1*W1)
#define NT2   28            // conv2 tiles: 2 output rows each (56 rows / 2)

// conv1 output, channel-last packed: [imgexp][h][w][ic] uint32 = (bf16 hi | bf16 mid<<16)
__device__ uint32_t g_h1p[(size_t)2 * BATCH * PIX * C1];
// packed conv2 weights: [e][tap][part(hi,mid)][oc=128][ic=64] bf16
__device__ unsigned short g_w2pack[2 * 9 * 2 * 128 * 64];
// pool partials: [imgexp][oc][tile]
__device__ float g_pool[2 * BATCH * C2 * NT2];
// per-sample routing flag
__device__ int g_use2[BATCH];

__device__ __forceinline__ uint32_t pack_bf16_split(float v) {
    __nv_bfloat16 h = __float2bfloat16(v);
    float hf = __bfloat162float(h);
    __nv_bfloat16 m = __float2bfloat16(v - hf);
    return (uint32_t)__bfloat16_as_ushort(h) | ((uint32_t)__bfloat16_as_ushort(m) << 16);
}

// mma.sync m16n8k16 bf16 (baseline PTX, works on plain sm_103 target)
#define MMA_BF16(d, a, b) \
    asm volatile("mma.sync.aligned.m16n8k16.row.col.f32.bf16.bf16.f32 " \
        "{%0,%1,%2,%3}, {%4,%5,%6,%7}, {%8,%9}, {%0,%1,%2,%3};" \
        : "+f"((d)[0]), "+f"((d)[1]), "+f"((d)[2]), "+f"((d)[3]) \
        : "r"((a)[0]), "r"((a)[1]), "r"((a)[2]), "r"((a)[3]), \
          "r"((b)[0]), "r"((b)[1]))

// ---------------------------------------------------------------------------
// conv1: 3x3 s2 SAME + bias + ReLU, channel-last packed bf16-split output.
// grid(49 tiles of 16x16, 128 imgexp), block 256, thread = 1 pixel x 64 oc.
// ---------------------------------------------------------------------------
__global__ __launch_bounds__(256) void conv1_kernel(
    const float* __restrict__ x,
    const float* __restrict__ tw1, const float* __restrict__ tb1,
    const float* __restrict__ fw1, const float* __restrict__ fb1)
{
    __shared__ float sin[3][33][36];
    __shared__ float sw[27 * 64];

    const int tile = blockIdx.x;
    const int imgexp = blockIdx.y;
    const int e = imgexp >> 6;
    const int b = imgexp & 63;
    const float* w1 = e ? fw1 : tw1;
    const float* b1 = e ? fb1 : tb1;
    const int tid = threadIdx.x;

    const int ty0 = (tile / 7) * 16;
    const int tx0 = (tile % 7) * 16;

    for (int i = tid; i < 27 * 64; i += 256) {
        int k = i >> 6, oc = i & 63;
        sw[i] = w1[oc * 27 + k];
    }
    const int r0 = 2 * ty0, c0 = 2 * tx0;
    const float* xb = x + (size_t)b * 3 * H0 * W0;
    for (int i = tid; i < 3 * 33 * 33; i += 256) {
        int ic = i / 1089;
        int rem = i - ic * 1089;
        int r = rem / 33, c = rem - (rem / 33) * 33;
        int gr = r0 + r, gc = c0 + c;
        float v = 0.f;
        if (gr < H0 && gc < W0) v = xb[(size_t)ic * H0 * W0 + (size_t)gr * W0 + gc];
        sin[ic][r][c] = v;
    }
    __syncthreads();

    const int ty = tid >> 4, tx = tid & 15;
    float4 acc[16];
    const float4* b4 = (const float4*)b1;
    #pragma unroll
    for (int j = 0; j < 16; ++j) acc[j] = b4[j];

    #pragma unroll
    for (int ic = 0; ic < 3; ++ic) {
        float iv[9];
        #pragma unroll
        for (int dy = 0; dy < 3; ++dy)
            #pragma unroll
            for (int dx = 0; dx < 3; ++dx)
                iv[dy * 3 + dx] = sin[ic][2 * ty + dy][2 * tx + dx];
        #pragma unroll
        for (int k = 0; k < 9; ++k) {
            float v = iv[k];
            const float4* w4 = (const float4*)&sw[(ic * 9 + k) * 64];
            #pragma unroll
            for (int j = 0; j < 16; ++j) {
                float4 w = w4[j];
                acc[j].x += v * w.x; acc[j].y += v * w.y;
                acc[j].z += v * w.z; acc[j].w += v * w.w;
            }
        }
    }

    const int oh = ty0 + ty, ow = tx0 + tx;
    uint4* dst = (uint4*)(g_h1p + (size_t)imgexp * PIX * C1 + (size_t)(oh * W1 + ow) * C1);
    #pragma unroll
    for (int j = 0; j < 16; ++j) {
        uint4 o;
        o.x = pack_bf16_split(fmaxf(acc[j].x, 0.f));
        o.y = pack_bf16_split(fmaxf(acc[j].y, 0.f));
        o.z = pack_bf16_split(fmaxf(acc[j].z, 0.f));
        o.w = pack_bf16_split(fmaxf(acc[j].w, 0.f));
        dst[j] = o;
    }
}

// ---------------------------------------------------------------------------
// weight pack: w2[oc][ic][3][3] fp32 -> g_w2pack[e][tap][part][oc][ic] bf16
// ---------------------------------------------------------------------------
__global__ void pack_w2_kernel(const float* __restrict__ tw2, const float* __restrict__ fw2)
{
    int idx = blockIdx.x * blockDim.x + threadIdx.x;
    if (idx >= 2 * 9 * 128 * 64) return;
    int e   = idx / 73728;
    int rem = idx - e * 73728;
    int tap = rem / 8192;
    int rem2 = rem - tap * 8192;
    int oc = rem2 >> 6, ic = rem2 & 63;
    float w = (e ? fw2 : tw2)[oc * 576 + ic * 9 + tap];
    __nv_bfloat16 h = __float2bfloat16(w);
    float hf = __bfloat162float(h);
    __nv_bfloat16 m = __float2bfloat16(w - hf);
    size_t base = (((size_t)(e * 9 + tap) * 2) * 128 + oc) * 64 + ic;
    g_w2pack[base]            = __bfloat16_as_ushort(h);
    g_w2pack[base + 128 * 64] = __bfloat16_as_ushort(m);
}

// ---------------------------------------------------------------------------
// conv2 via mma.sync (HMMA): CTA = (imgexp, 2-output-row tile): M=128 x N=112
// 8 warps (4 M x 2 N), warp tile 32 x 56, bf16-split 3-combo accumulation.
// A single-buffered (restaged per tap, exposed), B double-buffered (overlapped).
// smem total 102400 B -> 2 CTAs/SM so cross-CTA overlap hides sync bubbles.
// ---------------------------------------------------------------------------
#define A_BYTES       36864                        // 2 parts * 128 * 144
#define B_OFF2        36864
#define B_BUF_BYTES   32256                        // 2 parts * 112 * 144
#define SRED_OFF      (B_OFF2 + 2 * B_BUF_BYTES)   // 101376
#define SMEM2_BYTES   (SRED_OFF + 128 * 2 * 4)     // 102400

__global__ __launch_bounds__(256, 2) void conv2_mma_kernel(
    const float* __restrict__ tb2, const float* __restrict__ fb2)
{
    extern __shared__ char smem[];
    const int tid = threadIdx.x;
    const int wid = tid >> 5, lane = tid & 31;
    const int wm = wid & 3;          // M warp: 32*wm
    const int wn = wid >> 2;         // N warp: 56*wn
    const int tileIdx = blockIdx.x;  // 0..27
    const int imgexp  = blockIdx.y;  // 0..127
    const int e = imgexp >> 6;
    const int oh0 = tileIdx * 2;

    const uint4* wsrc = (const uint4*)g_w2pack + (size_t)e * 9 * 2048;
    const uint4* src  = (const uint4*)g_h1p + (size_t)imgexp * PIX * 16;

    float acc[2][7][4];
    #pragma unroll
    for (int mt = 0; mt < 2; ++mt)
        #pragma unroll
        for (int nt = 0; nt < 7; ++nt)
            #pragma unroll
            for (int j = 0; j < 4; ++j) acc[mt][nt][j] = 0.f;

    auto stageA = [&](int t) {
        const uint4* ws = wsrc + t * 2048;
        #pragma unroll
        for (int ii = 0; ii < 8; ++ii) {
            int i = tid + ii * 256;              // 0..2047
            int part = i >> 10, idx = i & 1023;
            int row = idx >> 3, col = idx & 7;
            *(uint4*)(smem + part * 18432 + row * 144 + col * 16) = ws[i];
        }
    };
    auto stageB = [&](int t, int buf) {
        const int dy = t / 3, dx = t - (t / 3) * 3;
        char* bb = smem + B_OFF2 + buf * B_BUF_BYTES;
        #pragma unroll
        for (int ii = 0; ii < 7; ++ii) {
            int i = tid + ii * 256;              // 0..1791
            int n = i >> 4, icq = i & 15;
            int ohl = (n >= 56) ? 1 : 0;
            int ow = n - ohl * 56;
            int ih = 2 * (oh0 + ohl) + dy;
            int iw = 2 * ow + dx;
            uint4 v = make_uint4(0u, 0u, 0u, 0u);
            if (ih < H1 && iw < W1) v = src[(ih * W1 + iw) * 16 + icq];
            uint32_t off = (uint32_t)(n * 144 + icq * 8);
            uint2 h, m;
            h.x = (v.x & 0xffffu) | (v.y << 16);
            h.y = (v.z & 0xffffu) | (v.w << 16);
            m.x = (v.x >> 16) | (v.y & 0xffff0000u);
            m.y = (v.z >> 16) | (v.w & 0xffff0000u);
            *(uint2*)(bb + off) = h;
            *(uint2*)(bb + 16128 + off) = m;
        }
    };

    stageA(0);
    stageB(0, 0);
    __syncthreads();

    const int mrow = lane >> 2;
    const int koff = (lane & 3) * 4;

    for (int t = 0; t < 9; ++t) {
        const int buf = t & 1;
        if (t < 8) stageB(t + 1, buf ^ 1);   // overlaps compute(t)

        const char* bb = smem + B_OFF2 + buf * B_BUF_BYTES;
        const char* aptr = smem + (wm * 32 + mrow) * 144 + koff;
        const char* bptr = bb + (wn * 56 + mrow) * 144 + koff;

        #pragma unroll
        for (int kk = 0; kk < 4; ++kk) {
            uint32_t Ah[2][4], Am[2][4];
            #pragma unroll
            for (int mt = 0; mt < 2; ++mt) {
                const char* p = aptr + mt * (16 * 144) + kk * 32;
                Ah[mt][0] = *(const uint32_t*)(p);
                Ah[mt][1] = *(const uint32_t*)(p + 8 * 144);
                Ah[mt][2] = *(const uint32_t*)(p + 16);
                Ah[mt][3] = *(const uint32_t*)(p + 8 * 144 + 16);
                const char* q = p + 18432;
                Am[mt][0] = *(const uint32_t*)(q);
                Am[mt][1] = *(const uint32_t*)(q + 8 * 144);
                Am[mt][2] = *(const uint32_t*)(q + 16);
                Am[mt][3] = *(const uint32_t*)(q + 8 * 144 + 16);
            }
            uint32_t Bh[7][2], Bm[7][2];
            #pragma unroll
            for (int nt = 0; nt < 7; ++nt) {
                const char* p = bptr + nt * (8 * 144) + kk * 32;
                Bh[nt][0] = *(const uint32_t*)(p);
                Bh[nt][1] = *(const uint32_t*)(p + 16);
                const char* q = p + 16128;
                Bm[nt][0] = *(const uint32_t*)(q);
                Bm[nt][1] = *(const uint32_t*)(q + 16);
            }
            #pragma unroll
            for (int mt = 0; mt < 2; ++mt)
                #pragma unroll
                for (int nt = 0; nt < 7; ++nt) {
                    MMA_BF16(acc[mt][nt], Ah[mt], Bh[nt]);
                    MMA_BF16(acc[mt][nt], Ah[mt], Bm[nt]);
                    MMA_BF16(acc[mt][nt], Am[mt], Bh[nt]);
                }
        }
        __syncthreads();                     // compute(t) done; B(t+1) staged
        if (t < 8) {
            stageA(t + 1);                   // safe: all readers past A
            __syncthreads();
        }
    }

    // epilogue: bias + relu per element, deterministic pooled partial per oc
    float* sred = (float*)(smem + SRED_OFF);
    const float* b2 = e ? fb2 : tb2;
    #pragma unroll
    for (int mt = 0; mt < 2; ++mt) {
        int m0 = wm * 32 + mt * 16 + mrow;
        float bias0 = b2[m0], bias1 = b2[m0 + 8];
        float s0 = 0.f, s1 = 0.f;
        #pragma unroll
        for (int nt = 0; nt < 7; ++nt) {
            s0 += fmaxf(acc[mt][nt][0] + bias0, 0.f) + fmaxf(acc[mt][nt][1] + bias0, 0.f);
            s1 += fmaxf(acc[mt][nt][2] + bias1, 0.f) + fmaxf(acc[mt][nt][3] + bias1, 0.f);
        }
        s0 += __shfl_xor_sync(0xffffffffu, s0, 1);
        s0 += __shfl_xor_sync(0xffffffffu, s0, 2);
        s1 += __shfl_xor_sync(0xffffffffu, s1, 1);
        s1 += __shfl_xor_sync(0xffffffffu, s1, 2);
        if ((lane & 3) == 0) {
            sred[m0 * 2 + wn] = s0;
            sred[(m0 + 8) * 2 + wn] = s1;
        }
    }
    __syncthreads();
    if (tid < 128)
        g_pool[((size_t)imgexp * C2 + tid) * NT2 + tileIdx] = sred[tid * 2] + sred[tid * 2 + 1];
}

// ---------------------------------------------------------------------------
// head: grid(64 samples) x 128 threads (one per oc). Deterministic tree reduce.
// ---------------------------------------------------------------------------
__global__ __launch_bounds__(128) void head_kernel(
    const float* __restrict__ twf, const float* __restrict__ tbf,
    const float* __restrict__ fwf, const float* __restrict__ fbf,
    float* __restrict__ out)
{
    __shared__ float s0[128], s1[128], s2[128], s3[128];
    const int b  = blockIdx.x;
    const int oc = threadIdx.x;
    const float inv = 1.f / 3136.f;

    const float* pt = &g_pool[((size_t)b * C2 + oc) * NT2];
    float gt = 0.f;
    #pragma unroll
    for (int k = 0; k < NT2; ++k) gt += pt[k];
    gt *= inv;
    const float* pf = &g_pool[((size_t)(BATCH + b) * C2 + oc) * NT2];
    float gf = 0.f;
    #pragma unroll
    for (int k = 0; k < NT2; ++k) gf += pf[k];
    gf *= inv;

    s0[oc] = gt * twf[oc * 2 + 0];
    s1[oc] = gt * twf[oc * 2 + 1];
    s2[oc] = gf * fwf[oc * 2 + 0];
    s3[oc] = gf * fwf[oc * 2 + 1];
    __syncthreads();

    #pragma unroll
    for (int stride = 64; stride > 0; stride >>= 1) {
        if (oc < stride) {
            s0[oc] += s0[oc + stride];
            s1[oc] += s1[oc + stride];
            s2[oc] += s2[oc + stride];
            s3[oc] += s3[oc + stride];
        }
        __syncthreads();
    }

    if (oc == 0) {
        float tl0 = s0[0] + tbf[0], tl1 = s1[0] + tbf[1];
        float fl0 = s2[0] + fbf[0], fl1 = s3[0] + fbf[1];
        float conf = 1.f / (1.f + expf(-fabsf(tl0 - tl1)));
        bool use2 = (conf <= 0.9f);
        out[b * 2 + 0] = use2 ? (0.7f * tl0 + 0.3f * fl0) : tl0;
        out[b * 2 + 1] = use2 ? (0.7f * tl1 + 0.3f * fl1) : tl1;
        g_use2[b] = use2 ? 1 : 0;
    }
}

__global__ void finalize_kernel(float* __restrict__ out, int out_size)
{
    __shared__ int sc[BATCH];
    const int t = threadIdx.x;
    sc[t] = g_use2[t];
    __syncthreads();
    #pragma unroll
    for (int stride = 32; stride > 0; stride >>= 1) {
        if (t < stride) sc[t] += sc[t + stride];
        __syncthreads();
    }
    if (t == 0 && out_size > 2 * BATCH)
        out[2 * BATCH] = (float)sc[0] / (float)BATCH;
}

// ---------------------------------------------------------------------------
extern "C" void kernel_launch(void* const* d_in, const int* in_sizes, int n_in,
                              void* d_out, int out_size)
{
    const float* x    = (const float*)d_in[0];
    const float* t_w1 = (const float*)d_in[1];
    const float* t_b1 = (const float*)d_in[2];
    const float* t_w2 = (const float*)d_in[3];
    const float* t_b2 = (const float*)d_in[4];
    const float* t_wf = (const float*)d_in[5];
    const float* t_bf = (const float*)d_in[6];
    const float* f_w1 = (const float*)d_in[7];
    const float* f_b1 = (const float*)d_in[8];
    const float* f_w2 = (const float*)d_in[9];
    const float* f_b2 = (const float*)d_in[10];
    const float* f_wf = (const float*)d_in[11];
    const float* f_bf = (const float*)d_in[12];
    float* out = (float*)d_out;

    cudaFuncSetAttribute(conv2_mma_kernel, cudaFuncAttributeMaxDynamicSharedMemorySize, SMEM2_BYTES);

    pack_w2_kernel<<<144, 1024>>>(t_w2, f_w2);

    dim3 g1(49, 2 * BATCH);
    conv1_kernel<<<g1, 256>>>(x, t_w1, t_b1, f_w1, f_b1);

    dim3 g2(NT2, 2 * BATCH);
    conv2_mma_kernel<<<g2, 256, SMEM2_BYTES>>>(t_b2, f_b2);

    head_kernel<<<BATCH, 128>>>(t_wf, t_bf, f_wf, f_bf, out);
    finalize_kernel<<<1, BATCH>>>(out, out_size);
}

// round 8
// speedup vs baseline: 3.7460x; 1.0424x over previous
#include <cuda_runtime.h>
#include <cuda_bf16.h>
#include <math.h>
#include <stdint.h>

#define BATCH 64
#define C1    64
#define C2    128
#define H0    224
#define W0    224
#define H1    112
#define W1    112
#define PIX   (H1*W1)
#define NT2   28            // conv2 tiles: 2 output rows each (56 rows / 2)

// conv1 output, channel-last packed: [imgexp][h][w][ic] uint32 = (bf16 hi | bf16 mid<<16)
__device__ uint32_t g_h1p[(size_t)2 * BATCH * PIX * C1];
// packed conv2 weights: [e][tap][part(hi,mid)][oc=128][ic=64] bf16
__device__ unsigned short g_w2pack[2 * 9 * 2 * 128 * 64];
// pool partials: [imgexp][oc][tile]
__device__ float g_pool[2 * BATCH * C2 * NT2];
// per-sample routing flag
__device__ int g_use2[BATCH];

__device__ __forceinline__ uint32_t pack_bf16_split(float v) {
    __nv_bfloat16 h = __float2bfloat16(v);
    float hf = __bfloat162float(h);
    __nv_bfloat16 m = __float2bfloat16(v - hf);
    return (uint32_t)__bfloat16_as_ushort(h) | ((uint32_t)__bfloat16_as_ushort(m) << 16);
}

// mma.sync m16n8k16 bf16 (baseline PTX, works on plain sm_103 target)
#define MMA_BF16(d, a, b) \
    asm volatile("mma.sync.aligned.m16n8k16.row.col.f32.bf16.bf16.f32 " \
        "{%0,%1,%2,%3}, {%4,%5,%6,%7}, {%8,%9}, {%0,%1,%2,%3};" \
        : "+f"((d)[0]), "+f"((d)[1]), "+f"((d)[2]), "+f"((d)[3]) \
        : "r"((a)[0]), "r"((a)[1]), "r"((a)[2]), "r"((a)[3]), \
          "r"((b)[0]), "r"((b)[1]))

// ldmatrix (baseline PTX sm_75+)
#define LDMX4(R, A) \
    asm volatile("ldmatrix.sync.aligned.m8n8.x4.shared.b16 {%0,%1,%2,%3}, [%4];" \
        : "=r"((R)[0]), "=r"((R)[1]), "=r"((R)[2]), "=r"((R)[3]) : "r"(A))
#define LDMX4B(R0, R1, A) \
    asm volatile("ldmatrix.sync.aligned.m8n8.x4.shared.b16 {%0,%1,%2,%3}, [%4];" \
        : "=r"((R0)[0]), "=r"((R0)[1]), "=r"((R1)[0]), "=r"((R1)[1]) : "r"(A))
#define LDMX2(R, A) \
    asm volatile("ldmatrix.sync.aligned.m8n8.x2.shared.b16 {%0,%1}, [%2];" \
        : "=r"((R)[0]), "=r"((R)[1]) : "r"(A))

// ---------------------------------------------------------------------------
// conv1: 3x3 s2 SAME + bias + ReLU, channel-last packed bf16-split output.
// grid(49 tiles of 16x16, 128 imgexp), block 256, thread = 1 pixel x 64 oc.
// ---------------------------------------------------------------------------
__global__ __launch_bounds__(256) void conv1_kernel(
    const float* __restrict__ x,
    const float* __restrict__ tw1, const float* __restrict__ tb1,
    const float* __restrict__ fw1, const float* __restrict__ fb1)
{
    __shared__ float sin[3][33][36];
    __shared__ float sw[27 * 64];

    const int tile = blockIdx.x;
    const int imgexp = blockIdx.y;
    const int e = imgexp >> 6;
    const int b = imgexp & 63;
    const float* w1 = e ? fw1 : tw1;
    const float* b1 = e ? fb1 : tb1;
    const int tid = threadIdx.x;

    const int ty0 = (tile / 7) * 16;
    const int tx0 = (tile % 7) * 16;

    for (int i = tid; i < 27 * 64; i += 256) {
        int k = i >> 6, oc = i & 63;
        sw[i] = w1[oc * 27 + k];
    }
    const int r0 = 2 * ty0, c0 = 2 * tx0;
    const float* xb = x + (size_t)b * 3 * H0 * W0;
    for (int i = tid; i < 3 * 33 * 33; i += 256) {
        int ic = i / 1089;
        int rem = i - ic * 1089;
        int r = rem / 33, c = rem - (rem / 33) * 33;
        int gr = r0 + r, gc = c0 + c;
        float v = 0.f;
        if (gr < H0 && gc < W0) v = xb[(size_t)ic * H0 * W0 + (size_t)gr * W0 + gc];
        sin[ic][r][c] = v;
    }
    __syncthreads();

    const int ty = tid >> 4, tx = tid & 15;
    float4 acc[16];
    const float4* b4 = (const float4*)b1;
    #pragma unroll
    for (int j = 0; j < 16; ++j) acc[j] = b4[j];

    #pragma unroll
    for (int ic = 0; ic < 3; ++ic) {
        float iv[9];
        #pragma unroll
        for (int dy = 0; dy < 3; ++dy)
            #pragma unroll
            for (int dx = 0; dx < 3; ++dx)
                iv[dy * 3 + dx] = sin[ic][2 * ty + dy][2 * tx + dx];
        #pragma unroll
        for (int k = 0; k < 9; ++k) {
            float v = iv[k];
            const float4* w4 = (const float4*)&sw[(ic * 9 + k) * 64];
            #pragma unroll
            for (int j = 0; j < 16; ++j) {
                float4 w = w4[j];
                acc[j].x += v * w.x; acc[j].y += v * w.y;
                acc[j].z += v * w.z; acc[j].w += v * w.w;
            }
        }
    }

    const int oh = ty0 + ty, ow = tx0 + tx;
    uint4* dst = (uint4*)(g_h1p + (size_t)imgexp * PIX * C1 + (size_t)(oh * W1 + ow) * C1);
    #pragma unroll
    for (int j = 0; j < 16; ++j) {
        uint4 o;
        o.x = pack_bf16_split(fmaxf(acc[j].x, 0.f));
        o.y = pack_bf16_split(fmaxf(acc[j].y, 0.f));
        o.z = pack_bf16_split(fmaxf(acc[j].z, 0.f));
        o.w = pack_bf16_split(fmaxf(acc[j].w, 0.f));
        dst[j] = o;
    }
}

// ---------------------------------------------------------------------------
// weight pack: w2[oc][ic][3][3] fp32 -> g_w2pack[e][tap][part][oc][ic] bf16
// ---------------------------------------------------------------------------
__global__ void pack_w2_kernel(const float* __restrict__ tw2, const float* __restrict__ fw2)
{
    int idx = blockIdx.x * blockDim.x + threadIdx.x;
    if (idx >= 2 * 9 * 128 * 64) return;
    int e   = idx / 73728;
    int rem = idx - e * 73728;
    int tap = rem / 8192;
    int rem2 = rem - tap * 8192;
    int oc = rem2 >> 6, ic = rem2 & 63;
    float w = (e ? fw2 : tw2)[oc * 576 + ic * 9 + tap];
    __nv_bfloat16 h = __float2bfloat16(w);
    float hf = __bfloat162float(h);
    __nv_bfloat16 m = __float2bfloat16(w - hf);
    size_t base = (((size_t)(e * 9 + tap) * 2) * 128 + oc) * 64 + ic;
    g_w2pack[base]            = __bfloat16_as_ushort(h);
    g_w2pack[base + 128 * 64] = __bfloat16_as_ushort(m);
}

// ---------------------------------------------------------------------------
// conv2 via mma.sync (HMMA): CTA = (imgexp, 2-output-row tile): M=128 x N=112
// 8 warps (4 M x 2 N), warp tile 32 x 56, bf16-split 3-combo accumulation.
// Fragments via ldmatrix (12 instrs/kk vs 44 scalar LDS).
// A single-buffered, B double-buffered; 2 CTAs/SM hide sync bubbles.
// ---------------------------------------------------------------------------
#define A_BYTES       36864                        // 2 parts * 128 * 144
#define B_OFF2        36864
#define B_BUF_BYTES   32256                        // 2 parts * 112 * 144
#define SRED_OFF      (B_OFF2 + 2 * B_BUF_BYTES)   // 101376
#define SMEM2_BYTES   (SRED_OFF + 128 * 2 * 4)     // 102400

__global__ __launch_bounds__(256, 2) void conv2_mma_kernel(
    const float* __restrict__ tb2, const float* __restrict__ fb2)
{
    extern __shared__ char smem[];
    const int tid = threadIdx.x;
    const int wid = tid >> 5, lane = tid & 31;
    const int wm = wid & 3;          // M warp: 32*wm
    const int wn = wid >> 2;         // N warp: 56*wn
    const int tileIdx = blockIdx.x;  // 0..27
    const int imgexp  = blockIdx.y;  // 0..127
    const int e = imgexp >> 6;
    const int oh0 = tileIdx * 2;

    const uint4* wsrc = (const uint4*)g_w2pack + (size_t)e * 9 * 2048;
    const uint4* src  = (const uint4*)g_h1p + (size_t)imgexp * PIX * 16;

    float acc[2][7][4];
    #pragma unroll
    for (int mt = 0; mt < 2; ++mt)
        #pragma unroll
        for (int nt = 0; nt < 7; ++nt)
            #pragma unroll
            for (int j = 0; j < 4; ++j) acc[mt][nt][j] = 0.f;

    auto stageA = [&](int t) {
        const uint4* ws = wsrc + t * 2048;
        #pragma unroll
        for (int ii = 0; ii < 8; ++ii) {
            int i = tid + ii * 256;              // 0..2047
            int part = i >> 10, idx = i & 1023;
            int row = idx >> 3, col = idx & 7;
            *(uint4*)(smem + part * 18432 + row * 144 + col * 16) = ws[i];
        }
    };
    auto stageB = [&](int t, int buf) {
        const int dy = t / 3, dx = t - (t / 3) * 3;
        char* bb = smem + B_OFF2 + buf * B_BUF_BYTES;
        #pragma unroll
        for (int ii = 0; ii < 7; ++ii) {
            int i = tid + ii * 256;              // 0..1791
            int n = i >> 4, icq = i & 15;
            int ohl = (n >= 56) ? 1 : 0;
            int ow = n - ohl * 56;
            int ih = 2 * (oh0 + ohl) + dy;
            int iw = 2 * ow + dx;
            uint4 v = make_uint4(0u, 0u, 0u, 0u);
            if (ih < H1 && iw < W1) v = src[(ih * W1 + iw) * 16 + icq];
            uint32_t off = (uint32_t)(n * 144 + icq * 8);
            uint2 h, m;
            h.x = (v.x & 0xffffu) | (v.y << 16);
            h.y = (v.z & 0xffffu) | (v.w << 16);
            m.x = (v.x >> 16) | (v.y & 0xffff0000u);
            m.y = (v.z >> 16) | (v.w & 0xffff0000u);
            *(uint2*)(bb + off) = h;
            *(uint2*)(bb + 16128 + off) = m;
        }
    };

    stageA(0);
    stageB(0, 0);

    // ---- per-lane ldmatrix base addresses ----
    const uint32_t smem_u32 = (uint32_t)__cvta_generic_to_shared(smem);
    // A: lanes 0-7 rows 0-7 col0 | 8-15 rows 8-15 col0 | 16-23 rows 0-7 col16 | 24-31 rows 8-15 col16
    const int a_row = (lane & 7) + ((lane >> 3) & 1) * 8;
    const int a_col = (lane >> 4) * 16;
    uint32_t aoffH[2], aoffM[2];
    #pragma unroll
    for (int mt = 0; mt < 2; ++mt) {
        uint32_t r = (uint32_t)((wm * 32 + mt * 16 + a_row) * 144 + a_col);
        aoffH[mt] = smem_u32 + r;
        aoffM[mt] = smem_u32 + 18432 + r;
    }
    // B x4 (two 8-row n-tiles): lanes 0-7 nt0 col0 | 8-15 nt0 col16 | 16-23 nt1 col0 | 24-31 nt1 col16
    const int b_row = (lane & 7) + ((lane >> 4) & 1) * 8;
    const int b_col = ((lane >> 3) & 1) * 16;
    uint32_t boff[3];
    #pragma unroll
    for (int j = 0; j < 3; ++j)
        boff[j] = smem_u32 + B_OFF2 + (uint32_t)((wn * 56 + j * 16 + b_row) * 144 + b_col);
    // B x2 (last tile, nt=6): lanes 0-7 col0 | 8-15 col16 (lanes 16-31 mirror)
    const int b6_row = (lane & 7);
    const int b6_col = ((lane >> 3) & 1) * 16;
    const uint32_t boff6 = smem_u32 + B_OFF2 + (uint32_t)((wn * 56 + 48 + b6_row) * 144 + b6_col);

    __syncthreads();

    for (int t = 0; t < 9; ++t) {
        const int buf = t & 1;
        if (t < 8) stageB(t + 1, buf ^ 1);   // overlaps compute(t)

        const uint32_t bufoff = (uint32_t)(buf * B_BUF_BYTES);

        #pragma unroll
        for (int kk = 0; kk < 4; ++kk) {
            const uint32_t kb = (uint32_t)(kk * 32);
            uint32_t Ah[2][4], Am[2][4];
            #pragma unroll
            for (int mt = 0; mt < 2; ++mt) {
                LDMX4(Ah[mt], aoffH[mt] + kb);
                LDMX4(Am[mt], aoffM[mt] + kb);
            }
            uint32_t Bh[7][2], Bm[7][2];
            #pragma unroll
            for (int j = 0; j < 3; ++j) {
                LDMX4B(Bh[2 * j], Bh[2 * j + 1], boff[j] + bufoff + kb);
                LDMX4B(Bm[2 * j], Bm[2 * j + 1], boff[j] + bufoff + 16128 + kb);
            }
            LDMX2(Bh[6], boff6 + bufoff + kb);
            LDMX2(Bm[6], boff6 + bufoff + 16128 + kb);

            #pragma unroll
            for (int mt = 0; mt < 2; ++mt)
                #pragma unroll
                for (int nt = 0; nt < 7; ++nt) {
                    MMA_BF16(acc[mt][nt], Ah[mt], Bh[nt]);
                    MMA_BF16(acc[mt][nt], Ah[mt], Bm[nt]);
                    MMA_BF16(acc[mt][nt], Am[mt], Bh[nt]);
                }
        }
        __syncthreads();                     // compute(t) done; B(t+1) staged
        if (t < 8) {
            stageA(t + 1);                   // safe: all readers past A
            __syncthreads();
        }
    }

    // epilogue: bias + relu per element, deterministic pooled partial per oc
    float* sred = (float*)(smem + SRED_OFF);
    const float* b2 = e ? fb2 : tb2;
    const int mrow = lane >> 2;
    #pragma unroll
    for (int mt = 0; mt < 2; ++mt) {
        int m0 = wm * 32 + mt * 16 + mrow;
        float bias0 = b2[m0], bias1 = b2[m0 + 8];
        float s0 = 0.f, s1 = 0.f;
        #pragma unroll
        for (int nt = 0; nt < 7; ++nt) {
            s0 += fmaxf(acc[mt][nt][0] + bias0, 0.f) + fmaxf(acc[mt][nt][1] + bias0, 0.f);
            s1 += fmaxf(acc[mt][nt][2] + bias1, 0.f) + fmaxf(acc[mt][nt][3] + bias1, 0.f);
        }
        s0 += __shfl_xor_sync(0xffffffffu, s0, 1);
        s0 += __shfl_xor_sync(0xffffffffu, s0, 2);
        s1 += __shfl_xor_sync(0xffffffffu, s1, 1);
        s1 += __shfl_xor_sync(0xffffffffu, s1, 2);
        if ((lane & 3) == 0) {
            sred[m0 * 2 + wn] = s0;
            sred[(m0 + 8) * 2 + wn] = s1;
        }
    }
    __syncthreads();
    if (tid < 128)
        g_pool[((size_t)imgexp * C2 + tid) * NT2 + tileIdx] = sred[tid * 2] + sred[tid * 2 + 1];
}

// ---------------------------------------------------------------------------
// head: grid(64 samples) x 128 threads (one per oc). Deterministic tree reduce.
// ---------------------------------------------------------------------------
__global__ __launch_bounds__(128) void head_kernel(
    const float* __restrict__ twf, const float* __restrict__ tbf,
    const float* __restrict__ fwf, const float* __restrict__ fbf,
    float* __restrict__ out)
{
    __shared__ float s0[128], s1[128], s2[128], s3[128];
    const int b  = blockIdx.x;
    const int oc = threadIdx.x;
    const float inv = 1.f / 3136.f;

    const float* pt = &g_pool[((size_t)b * C2 + oc) * NT2];
    float gt = 0.f;
    #pragma unroll
    for (int k = 0; k < NT2; ++k) gt += pt[k];
    gt *= inv;
    const float* pf = &g_pool[((size_t)(BATCH + b) * C2 + oc) * NT2];
    float gf = 0.f;
    #pragma unroll
    for (int k = 0; k < NT2; ++k) gf += pf[k];
    gf *= inv;

    s0[oc] = gt * twf[oc * 2 + 0];
    s1[oc] = gt * twf[oc * 2 + 1];
    s2[oc] = gf * fwf[oc * 2 + 0];
    s3[oc] = gf * fwf[oc * 2 + 1];
    __syncthreads();

    #pragma unroll
    for (int stride = 64; stride > 0; stride >>= 1) {
        if (oc < stride) {
            s0[oc] += s0[oc + stride];
            s1[oc] += s1[oc + stride];
            s2[oc] += s2[oc + stride];
            s3[oc] += s3[oc + stride];
        }
        __syncthreads();
    }

    if (oc == 0) {
        float tl0 = s0[0] + tbf[0], tl1 = s1[0] + tbf[1];
        float fl0 = s2[0] + fbf[0], fl1 = s3[0] + fbf[1];
        float conf = 1.f / (1.f + expf(-fabsf(tl0 - tl1)));
        bool use2 = (conf <= 0.9f);
        out[b * 2 + 0] = use2 ? (0.7f * tl0 + 0.3f * fl0) : tl0;
        out[b * 2 + 1] = use2 ? (0.7f * tl1 + 0.3f * fl1) : tl1;
        g_use2[b] = use2 ? 1 : 0;
    }
}

__global__ void finalize_kernel(float* __restrict__ out, int out_size)
{
    __shared__ int sc[BATCH];
    const int t = threadIdx.x;
    sc[t] = g_use2[t];
    __syncthreads();
    #pragma unroll
    for (int stride = 32; stride > 0; stride >>= 1) {
        if (t < stride) sc[t] += sc[t + stride];
        __syncthreads();
    }
    if (t == 0 && out_size > 2 * BATCH)
        out[2 * BATCH] = (float)sc[0] / (float)BATCH;
}

// ---------------------------------------------------------------------------
extern "C" void kernel_launch(void* const* d_in, const int* in_sizes, int n_in,
                              void* d_out, int out_size)
{
    const float* x    = (const float*)d_in[0];
    const float* t_w1 = (const float*)d_in[1];
    const float* t_b1 = (const float*)d_in[2];
    const float* t_w2 = (const float*)d_in[3];
    const float* t_b2 = (const float*)d_in[4];
    const float* t_wf = (const float*)d_in[5];
    const float* t_bf = (const float*)d_in[6];
    const float* f_w1 = (const float*)d_in[7];
    const float* f_b1 = (const float*)d_in[8];
    const float* f_w2 = (const float*)d_in[9];
    const float* f_b2 = (const float*)d_in[10];
    const float* f_wf = (const float*)d_in[11];
    const float* f_bf = (const float*)d_in[12];
    float* out = (float*)d_out;

    cudaFuncSetAttribute(conv2_mma_kernel, cudaFuncAttributeMaxDynamicSharedMemorySize, SMEM2_BYTES);

    pack_w2_kernel<<<144, 1024>>>(t_w2, f_w2);

    dim3 g1(49, 2 * BATCH);
    conv1_kernel<<<g1, 256>>>(x, t_w1, t_b1, f_w1, f_b1);

    dim3 g2(NT2, 2 * BATCH);
    conv2_mma_kernel<<<g2, 256, SMEM2_BYTES>>>(t_b2, f_b2);

    head_kernel<<<BATCH, 128>>>(t_wf, t_bf, f_wf, f_bf, out);
    finalize_kernel<<<1, BATCH>>>(out, out_size);
}

// round 9
// speedup vs baseline: 5.0732x; 1.3543x over previous
#include <cuda_runtime.h>
#include <cuda_fp16.h>
#include <math.h>
#include <stdint.h>

#define BATCH 64
#define C1    64
#define C2    128
#define H0    224
#define W0    224
#define H1    112
#define W1    112
#define PIX   (H1*W1)
#define NT2   28            // conv2 tiles: 2 output rows each (56 rows / 2)

// conv1 output, channel-last fp16: [imgexp][h][w][ic]
__device__ unsigned short g_h1f[(size_t)2 * BATCH * PIX * C1];
// packed conv2 weights fp16 split: [e][tap][part(hi,mid)][oc=128][ic=64]
__device__ unsigned short g_w2pack[2 * 9 * 2 * 128 * 64];
// pool partials: [imgexp][oc][tile]
__device__ float g_pool[2 * BATCH * C2 * NT2];
// per-sample routing flag
__device__ int g_use2[BATCH];

// mma.sync m16n8k16 fp16 (baseline PTX, works on plain sm_103 target)
#define MMA_F16(d, a, b) \
    asm volatile("mma.sync.aligned.m16n8k16.row.col.f32.f16.f16.f32 " \
        "{%0,%1,%2,%3}, {%4,%5,%6,%7}, {%8,%9}, {%0,%1,%2,%3};" \
        : "+f"((d)[0]), "+f"((d)[1]), "+f"((d)[2]), "+f"((d)[3]) \
        : "r"((a)[0]), "r"((a)[1]), "r"((a)[2]), "r"((a)[3]), \
          "r"((b)[0]), "r"((b)[1]))

// ldmatrix (baseline PTX sm_75+)
#define LDMX4(R, A) \
    asm volatile("ldmatrix.sync.aligned.m8n8.x4.shared.b16 {%0,%1,%2,%3}, [%4];" \
        : "=r"((R)[0]), "=r"((R)[1]), "=r"((R)[2]), "=r"((R)[3]) : "r"(A))
#define LDMX4B(R0, R1, A) \
    asm volatile("ldmatrix.sync.aligned.m8n8.x4.shared.b16 {%0,%1,%2,%3}, [%4];" \
        : "=r"((R0)[0]), "=r"((R0)[1]), "=r"((R1)[0]), "=r"((R1)[1]) : "r"(A))
#define LDMX2(R, A) \
    asm volatile("ldmatrix.sync.aligned.m8n8.x2.shared.b16 {%0,%1}, [%2];" \
        : "=r"((R)[0]), "=r"((R)[1]) : "r"(A))

__device__ __forceinline__ uint32_t pack_h2(float lo, float hi) {
    __half2 h = __floats2half2_rn(lo, hi);
    return *(uint32_t*)&h;
}

// ---------------------------------------------------------------------------
// conv1: 3x3 s2 SAME + bias + ReLU, channel-last fp16 output.
// grid(49 tiles of 16x16, 128 imgexp), block 256, thread = 1 pixel x 64 oc.
// ---------------------------------------------------------------------------
__global__ __launch_bounds__(256) void conv1_kernel(
    const float* __restrict__ x,
    const float* __restrict__ tw1, const float* __restrict__ tb1,
    const float* __restrict__ fw1, const float* __restrict__ fb1)
{
    __shared__ float sin[3][33][36];
    __shared__ float sw[27 * 64];

    const int tile = blockIdx.x;
    const int imgexp = blockIdx.y;
    const int e = imgexp >> 6;
    const int b = imgexp & 63;
    const float* w1 = e ? fw1 : tw1;
    const float* b1 = e ? fb1 : tb1;
    const int tid = threadIdx.x;

    const int ty0 = (tile / 7) * 16;
    const int tx0 = (tile % 7) * 16;

    for (int i = tid; i < 27 * 64; i += 256) {
        int k = i >> 6, oc = i & 63;
        sw[i] = w1[oc * 27 + k];
    }
    const int r0 = 2 * ty0, c0 = 2 * tx0;
    const float* xb = x + (size_t)b * 3 * H0 * W0;
    for (int i = tid; i < 3 * 33 * 33; i += 256) {
        int ic = i / 1089;
        int rem = i - ic * 1089;
        int r = rem / 33, c = rem - (rem / 33) * 33;
        int gr = r0 + r, gc = c0 + c;
        float v = 0.f;
        if (gr < H0 && gc < W0) v = xb[(size_t)ic * H0 * W0 + (size_t)gr * W0 + gc];
        sin[ic][r][c] = v;
    }
    __syncthreads();

    const int ty = tid >> 4, tx = tid & 15;
    float4 acc[16];
    const float4* b4 = (const float4*)b1;
    #pragma unroll
    for (int j = 0; j < 16; ++j) acc[j] = b4[j];

    #pragma unroll
    for (int ic = 0; ic < 3; ++ic) {
        float iv[9];
        #pragma unroll
        for (int dy = 0; dy < 3; ++dy)
            #pragma unroll
            for (int dx = 0; dx < 3; ++dx)
                iv[dy * 3 + dx] = sin[ic][2 * ty + dy][2 * tx + dx];
        #pragma unroll
        for (int k = 0; k < 9; ++k) {
            float v = iv[k];
            const float4* w4 = (const float4*)&sw[(ic * 9 + k) * 64];
            #pragma unroll
            for (int j = 0; j < 16; ++j) {
                float4 w = w4[j];
                acc[j].x += v * w.x; acc[j].y += v * w.y;
                acc[j].z += v * w.z; acc[j].w += v * w.w;
            }
        }
    }

    const int oh = ty0 + ty, ow = tx0 + tx;
    uint4* dst = (uint4*)(g_h1f + (size_t)imgexp * PIX * C1 + (size_t)(oh * W1 + ow) * C1);
    #pragma unroll
    for (int g = 0; g < 8; ++g) {
        float4 a0 = acc[2 * g], a1 = acc[2 * g + 1];
        uint4 o;
        o.x = pack_h2(fmaxf(a0.x, 0.f), fmaxf(a0.y, 0.f));
        o.y = pack_h2(fmaxf(a0.z, 0.f), fmaxf(a0.w, 0.f));
        o.z = pack_h2(fmaxf(a1.x, 0.f), fmaxf(a1.y, 0.f));
        o.w = pack_h2(fmaxf(a1.z, 0.f), fmaxf(a1.w, 0.f));
        dst[g] = o;
    }
}

// ---------------------------------------------------------------------------
// weight pack: w2[oc][ic][3][3] fp32 -> g_w2pack[e][tap][part][oc][ic] fp16 split
// ---------------------------------------------------------------------------
__global__ void pack_w2_kernel(const float* __restrict__ tw2, const float* __restrict__ fw2)
{
    int idx = blockIdx.x * blockDim.x + threadIdx.x;
    if (idx >= 2 * 9 * 128 * 64) return;
    int e   = idx / 73728;
    int rem = idx - e * 73728;
    int tap = rem / 8192;
    int rem2 = rem - tap * 8192;
    int oc = rem2 >> 6, ic = rem2 & 63;
    float w = (e ? fw2 : tw2)[oc * 576 + ic * 9 + tap];
    __half h = __float2half_rn(w);
    float hf = __half2float(h);
    __half m = __float2half_rn(w - hf);
    size_t base = (((size_t)(e * 9 + tap) * 2) * 128 + oc) * 64 + ic;
    g_w2pack[base]            = __half_as_ushort(h);
    g_w2pack[base + 128 * 64] = __half_as_ushort(m);
}

// ---------------------------------------------------------------------------
// conv2 via mma.sync fp16: CTA = (imgexp, 2-output-row tile): M=128 x N=112
// 8 warps (4 M x 2 N), warp tile 32 x 56. fp16 split-A 2-combo: Ah*B + Am*B.
// A single-buffered (36864B), B double-buffered (2 x 16128B). 2 CTAs/SM.
// ---------------------------------------------------------------------------
#define A_BYTES       36864                        // 2 parts * 128 * 144
#define B_OFF2        36864
#define B_BUF_BYTES   16128                        // 112 * 144
#define SRED_OFF      (B_OFF2 + 2 * B_BUF_BYTES)   // 69120
#define SMEM2_BYTES   (SRED_OFF + 128 * 2 * 4)     // 70144

__global__ __launch_bounds__(256, 2) void conv2_mma_kernel(
    const float* __restrict__ tb2, const float* __restrict__ fb2)
{
    extern __shared__ char smem[];
    const int tid = threadIdx.x;
    const int wid = tid >> 5, lane = tid & 31;
    const int wm = wid & 3;          // M warp: 32*wm
    const int wn = wid >> 2;         // N warp: 56*wn
    const int tileIdx = blockIdx.x;  // 0..27
    const int imgexp  = blockIdx.y;  // 0..127
    const int e = imgexp >> 6;
    const int oh0 = tileIdx * 2;

    const uint4* wsrc = (const uint4*)g_w2pack + (size_t)e * 9 * 2048;
    const uint4* src  = (const uint4*)g_h1f + (size_t)imgexp * PIX * 8;

    float acc[2][7][4];
    #pragma unroll
    for (int mt = 0; mt < 2; ++mt)
        #pragma unroll
        for (int nt = 0; nt < 7; ++nt)
            #pragma unroll
            for (int j = 0; j < 4; ++j) acc[mt][nt][j] = 0.f;

    auto stageA = [&](int t) {
        const uint4* ws = wsrc + t * 2048;
        #pragma unroll
        for (int ii = 0; ii < 8; ++ii) {
            int i = tid + ii * 256;              // 0..2047
            int part = i >> 10, idx = i & 1023;
            int row = idx >> 3, col = idx & 7;
            *(uint4*)(smem + part * 18432 + row * 144 + col * 16) = ws[i];
        }
    };
    auto stageB = [&](int t, int buf) {
        const int dy = t / 3, dx = t - (t / 3) * 3;
        char* bb = smem + B_OFF2 + buf * B_BUF_BYTES;
        #pragma unroll
        for (int ii = 0; ii < 4; ++ii) {
            int i = tid + ii * 256;              // 0..895 used
            if (i < 896) {
                int n = i >> 3, icq = i & 7;
                int ohl = (n >= 56) ? 1 : 0;
                int ow = n - ohl * 56;
                int ih = 2 * (oh0 + ohl) + dy;
                int iw = 2 * ow + dx;
                uint4 v = make_uint4(0u, 0u, 0u, 0u);
                if (ih < H1 && iw < W1) v = src[(ih * W1 + iw) * 8 + icq];
                *(uint4*)(bb + n * 144 + icq * 16) = v;
            }
        }
    };

    stageA(0);
    stageB(0, 0);

    // ---- per-lane ldmatrix base addresses ----
    const uint32_t smem_u32 = (uint32_t)__cvta_generic_to_shared(smem);
    // A: lanes 0-7 rows 0-7 col0 | 8-15 rows 8-15 col0 | 16-23 rows 0-7 col16 | 24-31 rows 8-15 col16
    const int a_row = (lane & 7) + ((lane >> 3) & 1) * 8;
    const int a_col = (lane >> 4) * 16;
    uint32_t aoffH[2], aoffM[2];
    #pragma unroll
    for (int mt = 0; mt < 2; ++mt) {
        uint32_t r = (uint32_t)((wm * 32 + mt * 16 + a_row) * 144 + a_col);
        aoffH[mt] = smem_u32 + r;
        aoffM[mt] = smem_u32 + 18432 + r;
    }
    // B x4 (two 8-row n-tiles): lanes 0-7 nt0 col0 | 8-15 nt0 col16 | 16-23 nt1 col0 | 24-31 nt1 col16
    const int b_row = (lane & 7) + ((lane >> 4) & 1) * 8;
    const int b_col = ((lane >> 3) & 1) * 16;
    uint32_t boff[3];
    #pragma unroll
    for (int j = 0; j < 3; ++j)
        boff[j] = smem_u32 + B_OFF2 + (uint32_t)((wn * 56 + j * 16 + b_row) * 144 + b_col);
    // B x2 (last tile, nt=6)
    const int b6_row = (lane & 7);
    const int b6_col = ((lane >> 3) & 1) * 16;
    const uint32_t boff6 = smem_u32 + B_OFF2 + (uint32_t)((wn * 56 + 48 + b6_row) * 144 + b6_col);

    __syncthreads();

    for (int t = 0; t < 9; ++t) {
        const int buf = t & 1;
        if (t < 8) stageB(t + 1, buf ^ 1);   // overlaps compute(t)

        const uint32_t bufoff = (uint32_t)(buf * B_BUF_BYTES);

        #pragma unroll
        for (int kk = 0; kk < 4; ++kk) {
            const uint32_t kb = (uint32_t)(kk * 32);
            uint32_t Ah[2][4], Am[2][4];
            #pragma unroll
            for (int mt = 0; mt < 2; ++mt) {
                LDMX4(Ah[mt], aoffH[mt] + kb);
                LDMX4(Am[mt], aoffM[mt] + kb);
            }
            uint32_t B[7][2];
            #pragma unroll
            for (int j = 0; j < 3; ++j)
                LDMX4B(B[2 * j], B[2 * j + 1], boff[j] + bufoff + kb);
            LDMX2(B[6], boff6 + bufoff + kb);

            #pragma unroll
            for (int mt = 0; mt < 2; ++mt)
                #pragma unroll
                for (int nt = 0; nt < 7; ++nt) {
                    MMA_F16(acc[mt][nt], Ah[mt], B[nt]);
                    MMA_F16(acc[mt][nt], Am[mt], B[nt]);
                }
        }
        __syncthreads();                     // compute(t) done; B(t+1) staged
        if (t < 8) {
            stageA(t + 1);                   // safe: all readers past A
            __syncthreads();
        }
    }

    // epilogue: bias + relu per element, deterministic pooled partial per oc
    float* sred = (float*)(smem + SRED_OFF);
    const float* b2 = e ? fb2 : tb2;
    const int mrow = lane >> 2;
    #pragma unroll
    for (int mt = 0; mt < 2; ++mt) {
        int m0 = wm * 32 + mt * 16 + mrow;
        float bias0 = b2[m0], bias1 = b2[m0 + 8];
        float s0 = 0.f, s1 = 0.f;
        #pragma unroll
        for (int nt = 0; nt < 7; ++nt) {
            s0 += fmaxf(acc[mt][nt][0] + bias0, 0.f) + fmaxf(acc[mt][nt][1] + bias0, 0.f);
            s1 += fmaxf(acc[mt][nt][2] + bias1, 0.f) + fmaxf(acc[mt][nt][3] + bias1, 0.f);
        }
        s0 += __shfl_xor_sync(0xffffffffu, s0, 1);
        s0 += __shfl_xor_sync(0xffffffffu, s0, 2);
        s1 += __shfl_xor_sync(0xffffffffu, s1, 1);
        s1 += __shfl_xor_sync(0xffffffffu, s1, 2);
        if ((lane & 3) == 0) {
            sred[m0 * 2 + wn] = s0;
            sred[(m0 + 8) * 2 + wn] = s1;
        }
    }
    __syncthreads();
    if (tid < 128)
        g_pool[((size_t)imgexp * C2 + tid) * NT2 + tileIdx] = sred[tid * 2] + sred[tid * 2 + 1];
}

// ---------------------------------------------------------------------------
// head: grid(64 samples) x 128 threads (one per oc). Deterministic tree reduce.
// ---------------------------------------------------------------------------
__global__ __launch_bounds__(128) void head_kernel(
    const float* __restrict__ twf, const float* __restrict__ tbf,
    const float* __restrict__ fwf, const float* __restrict__ fbf,
    float* __restrict__ out)
{
    __shared__ float s0[128], s1[128], s2[128], s3[128];
    const int b  = blockIdx.x;
    const int oc = threadIdx.x;
    const float inv = 1.f / 3136.f;

    const float* pt = &g_pool[((size_t)b * C2 + oc) * NT2];
    float gt = 0.f;
    #pragma unroll
    for (int k = 0; k < NT2; ++k) gt += pt[k];
    gt *= inv;
    const float* pf = &g_pool[((size_t)(BATCH + b) * C2 + oc) * NT2];
    float gf = 0.f;
    #pragma unroll
    for (int k = 0; k < NT2; ++k) gf += pf[k];
    gf *= inv;

    s0[oc] = gt * twf[oc * 2 + 0];
    s1[oc] = gt * twf[oc * 2 + 1];
    s2[oc] = gf * fwf[oc * 2 + 0];
    s3[oc] = gf * fwf[oc * 2 + 1];
    __syncthreads();

    #pragma unroll
    for (int stride = 64; stride > 0; stride >>= 1) {
        if (oc < stride) {
            s0[oc] += s0[oc + stride];
            s1[oc] += s1[oc + stride];
            s2[oc] += s2[oc + stride];
            s3[oc] += s3[oc + stride];
        }
        __syncthreads();
    }

    if (oc == 0) {
        float tl0 = s0[0] + tbf[0], tl1 = s1[0] + tbf[1];
        float fl0 = s2[0] + fbf[0], fl1 = s3[0] + fbf[1];
        float conf = 1.f / (1.f + expf(-fabsf(tl0 - tl1)));
        bool use2 = (conf <= 0.9f);
        out[b * 2 + 0] = use2 ? (0.7f * tl0 + 0.3f * fl0) : tl0;
        out[b * 2 + 1] = use2 ? (0.7f * tl1 + 0.3f * fl1) : tl1;
        g_use2[b] = use2 ? 1 : 0;
    }
}

__global__ void finalize_kernel(float* __restrict__ out, int out_size)
{
    __shared__ int sc[BATCH];
    const int t = threadIdx.x;
    sc[t] = g_use2[t];
    __syncthreads();
    #pragma unroll
    for (int stride = 32; stride > 0; stride >>= 1) {
        if (t < stride) sc[t] += sc[t + stride];
        __syncthreads();
    }
    if (t == 0 && out_size > 2 * BATCH)
        out[2 * BATCH] = (float)sc[0] / (float)BATCH;
}

// ---------------------------------------------------------------------------
extern "C" void kernel_launch(void* const* d_in, const int* in_sizes, int n_in,
                              void* d_out, int out_size)
{
    const float* x    = (const float*)d_in[0];
    const float* t_w1 = (const float*)d_in[1];
    const float* t_b1 = (const float*)d_in[2];
    const float* t_w2 = (const float*)d_in[3];
    const float* t_b2 = (const float*)d_in[4];
    const float* t_wf = (const float*)d_in[5];
    const float* t_bf = (const float*)d_in[6];
    const float* f_w1 = (const float*)d_in[7];
    const float* f_b1 = (const float*)d_in[8];
    const float* f_w2 = (const float*)d_in[9];
    const float* f_b2 = (const float*)d_in[10];
    const float* f_wf = (const float*)d_in[11];
    const float* f_bf = (const float*)d_in[12];
    float* out = (float*)d_out;

    cudaFuncSetAttribute(conv2_mma_kernel, cudaFuncAttributeMaxDynamicSharedMemorySize, SMEM2_BYTES);

    pack_w2_kernel<<<144, 1024>>>(t_w2, f_w2);

    dim3 g1(49, 2 * BATCH);
    conv1_kernel<<<g1, 256>>>(x, t_w1, t_b1, f_w1, f_b1);

    dim3 g2(NT2, 2 * BATCH);
    conv2_mma_kernel<<<g2, 256, SMEM2_BYTES>>>(t_b2, f_b2);

    head_kernel<<<BATCH, 128>>>(t_wf, t_bf, f_wf, f_bf, out);
    finalize_kernel<<<1, BATCH>>>(out, out_size);
}

// round 10
// speedup vs baseline: 6.9435x; 1.3687x over previous
#include <cuda_runtime.h>
#include <cuda_fp16.h>
#include <math.h>
#include <stdint.h>

#define BATCH 64
#define C1    64
#define C2    128
#define H0    224
#define W0    224
#define H1    112
#define W1    112
#define PIX   (H1*W1)
#define NT2   28            // conv2 tiles: 2 output rows each (56 rows / 2)

// conv1 output, channel-last fp16: [imgexp][h][w][ic]
__device__ unsigned short g_h1f[(size_t)2 * BATCH * PIX * C1];
// packed conv2 weights fp16 split: [e][tap][part(hi,mid)][oc=128][ic=64]
__device__ unsigned short g_w2pack[2 * 9 * 2 * 128 * 64];
// packed conv1 weights fp16 split: [part(hi,mid)][m=128 (t ocs then f ocs)][k=32]
__device__ unsigned short g_w1pack[2 * 128 * 32];
// pool partials: [imgexp][oc][tile]
__device__ float g_pool[2 * BATCH * C2 * NT2];
// per-sample routing flag
__device__ int g_use2[BATCH];

// mma.sync m16n8k16 fp16 (baseline PTX, works on plain sm_103 target)
#define MMA_F16(d, a, b) \
    asm volatile("mma.sync.aligned.m16n8k16.row.col.f32.f16.f16.f32 " \
        "{%0,%1,%2,%3}, {%4,%5,%6,%7}, {%8,%9}, {%0,%1,%2,%3};" \
        : "+f"((d)[0]), "+f"((d)[1]), "+f"((d)[2]), "+f"((d)[3]) \
        : "r"((a)[0]), "r"((a)[1]), "r"((a)[2]), "r"((a)[3]), \
          "r"((b)[0]), "r"((b)[1]))

// ldmatrix (baseline PTX sm_75+)
#define LDMX4(R, A) \
    asm volatile("ldmatrix.sync.aligned.m8n8.x4.shared.b16 {%0,%1,%2,%3}, [%4];" \
        : "=r"((R)[0]), "=r"((R)[1]), "=r"((R)[2]), "=r"((R)[3]) : "r"(A))
#define LDMX4B(R0, R1, A) \
    asm volatile("ldmatrix.sync.aligned.m8n8.x4.shared.b16 {%0,%1,%2,%3}, [%4];" \
        : "=r"((R0)[0]), "=r"((R0)[1]), "=r"((R1)[0]), "=r"((R1)[1]) : "r"(A))
#define LDMX2(R, A) \
    asm volatile("ldmatrix.sync.aligned.m8n8.x2.shared.b16 {%0,%1}, [%2];" \
        : "=r"((R)[0]), "=r"((R)[1]) : "r"(A))

__device__ __forceinline__ uint32_t pack_h2(float lo, float hi) {
    __half2 h = __floats2half2_rn(lo, hi);
    return *(uint32_t*)&h;
}

// ---------------------------------------------------------------------------
// weight pack (both convs): w2 -> split fp16 [e][tap][part][oc][ic];
// w1 -> split fp16 [part][m=128][k=32] (m: 64 t-ocs then 64 f-ocs, k 27..31 = 0)
// ---------------------------------------------------------------------------
__global__ void pack_weights_kernel(
    const float* __restrict__ tw2, const float* __restrict__ fw2,
    const float* __restrict__ tw1, const float* __restrict__ fw1)
{
    int idx = blockIdx.x * blockDim.x + threadIdx.x;
    if (idx < 2 * 9 * 128 * 64) {
        int e   = idx / 73728;
        int rem = idx - e * 73728;
        int tap = rem / 8192;
        int rem2 = rem - tap * 8192;
        int oc = rem2 >> 6, ic = rem2 & 63;
        float w = (e ? fw2 : tw2)[oc * 576 + ic * 9 + tap];
        __half h = __float2half_rn(w);
        __half m = __float2half_rn(w - __half2float(h));
        size_t base = (((size_t)(e * 9 + tap) * 2) * 128 + oc) * 64 + ic;
        g_w2pack[base]            = __half_as_ushort(h);
        g_w2pack[base + 128 * 64] = __half_as_ushort(m);
    } else {
        int j = idx - 2 * 9 * 128 * 64;
        if (j < 4096) {
            int m = j >> 5, k = j & 31;
            float w = 0.f;
            if (k < 27) w = (m < 64) ? tw1[m * 27 + k] : fw1[(m - 64) * 27 + k];
            __half h = __float2half_rn(w);
            __half mm = __float2half_rn(w - __half2float(h));
            g_w1pack[m * 32 + k]        = __half_as_ushort(h);
            g_w1pack[4096 + m * 32 + k] = __half_as_ushort(mm);
        }
    }
}

// ---------------------------------------------------------------------------
// conv1 via mma.sync fp16: CTA = (8x16 output tile, image b, BOTH experts).
// A = stacked weights M=128 (t|f), split hi/mid. B = im2col x fp16 (shared).
// 8 warps: wm in M (4 x 32), wn in N (2 x 64). 2 combos: Ah*B + Am*B.
// grid(98 tiles, 64 images), block 256.
// ---------------------------------------------------------------------------
#define SIN1_F    (3 * 17 * 36)              // floats
#define B_OFF1    7344                        // = SIN1_F*4
#define A_OFF1    (B_OFF1 + 128 * 80)         // 17584
#define SMEM1_BYTES (A_OFF1 + 2 * 128 * 80)   // 38064  (sout 128x272=34816 overlaps)
#define SOUT_STRIDE 136                       // halves (272 B)

__global__ __launch_bounds__(256) void conv1_mma_kernel(
    const float* __restrict__ x,
    const float* __restrict__ tb1, const float* __restrict__ fb1)
{
    extern __shared__ char smem[];
    float* sinp = (float*)smem;               // [3][17][36]
    const int tid = threadIdx.x;
    const int wid = tid >> 5, lane = tid & 31;
    const int wm = wid & 3;                   // M: 32*wm
    const int wn = wid >> 2;                  // N: 64*wn
    const int tile = blockIdx.x;              // 0..97
    const int b    = blockIdx.y;              // image

    const int ty0 = (tile / 7) * 8;
    const int tx0 = (tile % 7) * 16;

    // stage A: g_w1pack [2][128][32] halves = 1024 uint4; rows padded to 80B
    {
        const uint4* ws = (const uint4*)g_w1pack;
        #pragma unroll
        for (int ii = 0; ii < 4; ++ii) {
            int i = tid + ii * 256;           // 0..1023
            int part = i >> 9, idx = i & 511;
            int row = idx >> 2, col = idx & 3;
            *(uint4*)(smem + A_OFF1 + part * 10240 + row * 80 + col * 16) = ws[i];
        }
    }
    // stage input tile: rows 2*ty0..+16 (17), cols 2*tx0..+32 (33), 3 ch
    {
        const int r0 = 2 * ty0, c0 = 2 * tx0;
        const float* xb = x + (size_t)b * 3 * H0 * W0;
        for (int i = tid; i < 3 * 17 * 33; i += 256) {
            int ic = i / 561;
            int rem = i - ic * 561;
            int r = rem / 33, c = rem - (rem / 33) * 33;
            int gr = r0 + r, gc = c0 + c;
            float v = 0.f;
            if (gr < H0 && gc < W0) v = xb[(size_t)ic * H0 * W0 + (size_t)gr * W0 + gc];
            sinp[(ic * 17 + r) * 36 + c] = v;
        }
    }
    __syncthreads();

    // build B im2col: [128 n][32 k] fp16, row stride 80B. k = ic*9+dy*3+dx
    {
        const int n = tid >> 1;
        const int ohl = n >> 4, owl = n & 15;
        const int ib = 2 * ohl, jb = 2 * owl;
        char* brow = smem + B_OFF1 + n * 80;
        #define SIN1(icc, rr, cc) sinp[((icc) * 17 + (rr)) * 36 + (cc)]
        if ((tid & 1) == 0) {
            #pragma unroll
            for (int j = 0; j < 8; ++j) {
                const int k0 = 2 * j, k1 = k0 + 1;
                float v0 = SIN1(k0 / 9, ib + (k0 % 9) / 3, jb + k0 % 3);
                float v1 = SIN1(k1 / 9, ib + (k1 % 9) / 3, jb + k1 % 3);
                *(uint32_t*)(brow + k0 * 2) = pack_h2(v0, v1);
            }
        } else {
            #pragma unroll
            for (int j = 0; j < 8; ++j) {
                const int k0 = 16 + 2 * j, k1 = k0 + 1;
                float v0 = (k0 < 27) ? SIN1(k0 / 9, ib + (k0 % 9) / 3, jb + k0 % 3) : 0.f;
                float v1 = (k1 < 27) ? SIN1(k1 / 9, ib + (k1 % 9) / 3, jb + k1 % 3) : 0.f;
                *(uint32_t*)(brow + k0 * 2) = pack_h2(v0, v1);
            }
        }
        #undef SIN1
    }
    __syncthreads();

    // MMA: M128 x N128 x K32, 2 combos
    float acc[2][8][4];
    #pragma unroll
    for (int mt = 0; mt < 2; ++mt)
        #pragma unroll
        for (int nt = 0; nt < 8; ++nt)
            #pragma unroll
            for (int j = 0; j < 4; ++j) acc[mt][nt][j] = 0.f;

    const uint32_t smem_u32 = (uint32_t)__cvta_generic_to_shared(smem);
    const int a_row = (lane & 7) + ((lane >> 3) & 1) * 8;
    const int a_col = (lane >> 4) * 16;       // bytes
    uint32_t aoffH[2], aoffM[2];
    #pragma unroll
    for (int mt = 0; mt < 2; ++mt) {
        uint32_t r = (uint32_t)(A_OFF1 + (wm * 32 + mt * 16 + a_row) * 80 + a_col);
        aoffH[mt] = smem_u32 + r;
        aoffM[mt] = smem_u32 + r + 10240;
    }
    const int b_row = (lane & 7) + ((lane >> 4) & 1) * 8;
    const int b_col = ((lane >> 3) & 1) * 16; // bytes
    uint32_t boff[4];
    #pragma unroll
    for (int j = 0; j < 4; ++j)
        boff[j] = smem_u32 + (uint32_t)(B_OFF1 + (wn * 64 + j * 16 + b_row) * 80 + b_col);

    #pragma unroll
    for (int kk = 0; kk < 2; ++kk) {
        const uint32_t kb = (uint32_t)(kk * 32);
        uint32_t Ah[2][4], Am[2][4];
        #pragma unroll
        for (int mt = 0; mt < 2; ++mt) {
            LDMX4(Ah[mt], aoffH[mt] + kb);
            LDMX4(Am[mt], aoffM[mt] + kb);
        }
        uint32_t B[8][2];
        #pragma unroll
        for (int j = 0; j < 4; ++j)
            LDMX4B(B[2 * j], B[2 * j + 1], boff[j] + kb);
        #pragma unroll
        for (int mt = 0; mt < 2; ++mt)
            #pragma unroll
            for (int nt = 0; nt < 8; ++nt) {
                MMA_F16(acc[mt][nt], Ah[mt], B[nt]);
                MMA_F16(acc[mt][nt], Am[mt], B[nt]);
            }
    }
    __syncthreads();

    // epilogue: bias + ReLU -> fp16, transpose via smem sout[n][m] (stride 272B)
    __half* sh = (__half*)smem;
    {
        const int r = lane >> 2, c2 = (lane & 3) * 2;
        #pragma unroll
        for (int mt = 0; mt < 2; ++mt) {
            const int m0 = wm * 32 + mt * 16 + r;        // row for c0/c1
            const int m1 = m0 + 8;                       // row for c2/c3
            const float bias0 = (m0 < 64) ? tb1[m0] : fb1[m0 - 64];
            const float bias1 = (m1 < 64) ? tb1[m1] : fb1[m1 - 64];
            #pragma unroll
            for (int nt = 0; nt < 8; ++nt) {
                const int n0 = wn * 64 + nt * 8 + c2;
                sh[(n0)     * SOUT_STRIDE + m0] = __float2half_rn(fmaxf(acc[mt][nt][0] + bias0, 0.f));
                sh[(n0 + 1) * SOUT_STRIDE + m0] = __float2half_rn(fmaxf(acc[mt][nt][1] + bias0, 0.f));
                sh[(n0)     * SOUT_STRIDE + m1] = __float2half_rn(fmaxf(acc[mt][nt][2] + bias1, 0.f));
                sh[(n0 + 1) * SOUT_STRIDE + m1] = __float2half_rn(fmaxf(acc[mt][nt][3] + bias1, 0.f));
            }
        }
    }
    __syncthreads();

    // write out: both experts, channel-last [imgexp][pix][64]
    #pragma unroll
    for (int ii = 0; ii < 8; ++ii) {
        int i = tid + ii * 256;               // 0..2047
        int e2 = i >> 10, idx = i & 1023;
        int n = idx >> 3, q = idx & 7;
        int oh = ty0 + (n >> 4), ow = tx0 + (n & 15);
        uint4 v = *(const uint4*)(sh + n * SOUT_STRIDE + e2 * 64 + q * 8);
        size_t imgexp = (size_t)e2 * BATCH + b;
        *(uint4*)(g_h1f + imgexp * PIX * C1 + (size_t)(oh * W1 + ow) * C1 + q * 8) = v;
    }
}

// ---------------------------------------------------------------------------
// conv2 via mma.sync fp16: CTA = (imgexp, 2-output-row tile): M=128 x N=112
// 8 warps (4 M x 2 N), warp tile 32 x 56. fp16 split-A 2-combo: Ah*B + Am*B.
// A single-buffered (36864B), B double-buffered (2 x 16128B). 2 CTAs/SM.
// ---------------------------------------------------------------------------
#define A_BYTES       36864                        // 2 parts * 128 * 144
#define B_OFF2        36864
#define B_BUF_BYTES   16128                        // 112 * 144
#define SRED_OFF      (B_OFF2 + 2 * B_BUF_BYTES)   // 69120
#define SMEM2_BYTES   (SRED_OFF + 128 * 2 * 4)     // 70144

__global__ __launch_bounds__(256, 2) void conv2_mma_kernel(
    const float* __restrict__ tb2, const float* __restrict__ fb2)
{
    extern __shared__ char smem[];
    const int tid = threadIdx.x;
    const int wid = tid >> 5, lane = tid & 31;
    const int wm = wid & 3;          // M warp: 32*wm
    const int wn = wid >> 2;         // N warp: 56*wn
    const int tileIdx = blockIdx.x;  // 0..27
    const int imgexp  = blockIdx.y;  // 0..127
    const int e = imgexp >> 6;
    const int oh0 = tileIdx * 2;

    const uint4* wsrc = (const uint4*)g_w2pack + (size_t)e * 9 * 2048;
    const uint4* src  = (const uint4*)g_h1f + (size_t)imgexp * PIX * 8;

    float acc[2][7][4];
    #pragma unroll
    for (int mt = 0; mt < 2; ++mt)
        #pragma unroll
        for (int nt = 0; nt < 7; ++nt)
            #pragma unroll
            for (int j = 0; j < 4; ++j) acc[mt][nt][j] = 0.f;

    auto stageA = [&](int t) {
        const uint4* ws = wsrc + t * 2048;
        #pragma unroll
        for (int ii = 0; ii < 8; ++ii) {
            int i = tid + ii * 256;              // 0..2047
            int part = i >> 10, idx = i & 1023;
            int row = idx >> 3, col = idx & 7;
            *(uint4*)(smem + part * 18432 + row * 144 + col * 16) = ws[i];
        }
    };
    auto stageB = [&](int t, int buf) {
        const int dy = t / 3, dx = t - (t / 3) * 3;
        char* bb = smem + B_OFF2 + buf * B_BUF_BYTES;
        #pragma unroll
        for (int ii = 0; ii < 4; ++ii) {
            int i = tid + ii * 256;              // 0..895 used
            if (i < 896) {
                int n = i >> 3, icq = i & 7;
                int ohl = (n >= 56) ? 1 : 0;
                int ow = n - ohl * 56;
                int ih = 2 * (oh0 + ohl) + dy;
                int iw = 2 * ow + dx;
                uint4 v = make_uint4(0u, 0u, 0u, 0u);
                if (ih < H1 && iw < W1) v = src[(ih * W1 + iw) * 8 + icq];
                *(uint4*)(bb + n * 144 + icq * 16) = v;
            }
        }
    };

    stageA(0);
    stageB(0, 0);

    const uint32_t smem_u32 = (uint32_t)__cvta_generic_to_shared(smem);
    const int a_row = (lane & 7) + ((lane >> 3) & 1) * 8;
    const int a_col = (lane >> 4) * 16;
    uint32_t aoffH[2], aoffM[2];
    #pragma unroll
    for (int mt = 0; mt < 2; ++mt) {
        uint32_t r = (uint32_t)((wm * 32 + mt * 16 + a_row) * 144 + a_col);
        aoffH[mt] = smem_u32 + r;
        aoffM[mt] = smem_u32 + 18432 + r;
    }
    const int b_row = (lane & 7) + ((lane >> 4) & 1) * 8;
    const int b_col = ((lane >> 3) & 1) * 16;
    uint32_t boff[3];
    #pragma unroll
    for (int j = 0; j < 3; ++j)
        boff[j] = smem_u32 + B_OFF2 + (uint32_t)((wn * 56 + j * 16 + b_row) * 144 + b_col);
    const int b6_row = (lane & 7);
    const int b6_col = ((lane >> 3) & 1) * 16;
    const uint32_t boff6 = smem_u32 + B_OFF2 + (uint32_t)((wn * 56 + 48 + b6_row) * 144 + b6_col);

    __syncthreads();

    for (int t = 0; t < 9; ++t) {
        const int buf = t & 1;
        if (t < 8) stageB(t + 1, buf ^ 1);   // overlaps compute(t)

        const uint32_t bufoff = (uint32_t)(buf * B_BUF_BYTES);

        #pragma unroll
        for (int kk = 0; kk < 4; ++kk) {
            const uint32_t kb = (uint32_t)(kk * 32);
            uint32_t Ah[2][4], Am[2][4];
            #pragma unroll
            for (int mt = 0; mt < 2; ++mt) {
                LDMX4(Ah[mt], aoffH[mt] + kb);
                LDMX4(Am[mt], aoffM[mt] + kb);
            }
            uint32_t B[7][2];
            #pragma unroll
            for (int j = 0; j < 3; ++j)
                LDMX4B(B[2 * j], B[2 * j + 1], boff[j] + bufoff + kb);
            LDMX2(B[6], boff6 + bufoff + kb);

            #pragma unroll
            for (int mt = 0; mt < 2; ++mt)
                #pragma unroll
                for (int nt = 0; nt < 7; ++nt) {
                    MMA_F16(acc[mt][nt], Ah[mt], B[nt]);
                    MMA_F16(acc[mt][nt], Am[mt], B[nt]);
                }
        }
        __syncthreads();                     // compute(t) done; B(t+1) staged
        if (t < 8) {
            stageA(t + 1);                   // safe: all readers past A
            __syncthreads();
        }
    }

    // epilogue: bias + relu per element, deterministic pooled partial per oc
    float* sred = (float*)(smem + SRED_OFF);
    const float* b2 = e ? fb2 : tb2;
    const int mrow = lane >> 2;
    #pragma unroll
    for (int mt = 0; mt < 2; ++mt) {
        int m0 = wm * 32 + mt * 16 + mrow;
        float bias0 = b2[m0], bias1 = b2[m0 + 8];
        float s0 = 0.f, s1 = 0.f;
        #pragma unroll
        for (int nt = 0; nt < 7; ++nt) {
            s0 += fmaxf(acc[mt][nt][0] + bias0, 0.f) + fmaxf(acc[mt][nt][1] + bias0, 0.f);
            s1 += fmaxf(acc[mt][nt][2] + bias1, 0.f) + fmaxf(acc[mt][nt][3] + bias1, 0.f);
        }
        s0 += __shfl_xor_sync(0xffffffffu, s0, 1);
        s0 += __shfl_xor_sync(0xffffffffu, s0, 2);
        s1 += __shfl_xor_sync(0xffffffffu, s1, 1);
        s1 += __shfl_xor_sync(0xffffffffu, s1, 2);
        if ((lane & 3) == 0) {
            sred[m0 * 2 + wn] = s0;
            sred[(m0 + 8) * 2 + wn] = s1;
        }
    }
    __syncthreads();
    if (tid < 128)
        g_pool[((size_t)imgexp * C2 + tid) * NT2 + tileIdx] = sred[tid * 2] + sred[tid * 2 + 1];
}

// ---------------------------------------------------------------------------
// head: grid(64 samples) x 128 threads (one per oc). Deterministic tree reduce.
// ---------------------------------------------------------------------------
__global__ __launch_bounds__(128) void head_kernel(
    const float* __restrict__ twf, const float* __restrict__ tbf,
    const float* __restrict__ fwf, const float* __restrict__ fbf,
    float* __restrict__ out)
{
    __shared__ float s0[128], s1[128], s2[128], s3[128];
    const int b  = blockIdx.x;
    const int oc = threadIdx.x;
    const float inv = 1.f / 3136.f;

    const float* pt = &g_pool[((size_t)b * C2 + oc) * NT2];
    float gt = 0.f;
    #pragma unroll
    for (int k = 0; k < NT2; ++k) gt += pt[k];
    gt *= inv;
    const float* pf = &g_pool[((size_t)(BATCH + b) * C2 + oc) * NT2];
    float gf = 0.f;
    #pragma unroll
    for (int k = 0; k < NT2; ++k) gf += pf[k];
    gf *= inv;

    s0[oc] = gt * twf[oc * 2 + 0];
    s1[oc] = gt * twf[oc * 2 + 1];
    s2[oc] = gf * fwf[oc * 2 + 0];
    s3[oc] = gf * fwf[oc * 2 + 1];
    __syncthreads();

    #pragma unroll
    for (int stride = 64; stride > 0; stride >>= 1) {
        if (oc < stride) {
            s0[oc] += s0[oc + stride];
            s1[oc] += s1[oc + stride];
            s2[oc] += s2[oc + stride];
            s3[oc] += s3[oc + stride];
        }
        __syncthreads();
    }

    if (oc == 0) {
        float tl0 = s0[0] + tbf[0], tl1 = s1[0] + tbf[1];
        float fl0 = s2[0] + fbf[0], fl1 = s3[0] + fbf[1];
        float conf = 1.f / (1.f + expf(-fabsf(tl0 - tl1)));
        bool use2 = (conf <= 0.9f);
        out[b * 2 + 0] = use2 ? (0.7f * tl0 + 0.3f * fl0) : tl0;
        out[b * 2 + 1] = use2 ? (0.7f * tl1 + 0.3f * fl1) : tl1;
        g_use2[b] = use2 ? 1 : 0;
    }
}

__global__ void finalize_kernel(float* __restrict__ out, int out_size)
{
    __shared__ int sc[BATCH];
    const int t = threadIdx.x;
    sc[t] = g_use2[t];
    __syncthreads();
    #pragma unroll
    for (int stride = 32; stride > 0; stride >>= 1) {
        if (t < stride) sc[t] += sc[t + stride];
        __syncthreads();
    }
    if (t == 0 && out_size > 2 * BATCH)
        out[2 * BATCH] = (float)sc[0] / (float)BATCH;
}

// ---------------------------------------------------------------------------
extern "C" void kernel_launch(void* const* d_in, const int* in_sizes, int n_in,
                              void* d_out, int out_size)
{
    const float* x    = (const float*)d_in[0];
    const float* t_w1 = (const float*)d_in[1];
    const float* t_b1 = (const float*)d_in[2];
    const float* t_w2 = (const float*)d_in[3];
    const float* t_b2 = (const float*)d_in[4];
    const float* t_wf = (const float*)d_in[5];
    const float* t_bf = (const float*)d_in[6];
    const float* f_w1 = (const float*)d_in[7];
    const float* f_b1 = (const float*)d_in[8];
    const float* f_w2 = (const float*)d_in[9];
    const float* f_b2 = (const float*)d_in[10];
    const float* f_wf = (const float*)d_in[11];
    const float* f_bf = (const float*)d_in[12];
    float* out = (float*)d_out;

    cudaFuncSetAttribute(conv1_mma_kernel, cudaFuncAttributeMaxDynamicSharedMemorySize, SMEM1_BYTES);
    cudaFuncSetAttribute(conv2_mma_kernel, cudaFuncAttributeMaxDynamicSharedMemorySize, SMEM2_BYTES);

    pack_weights_kernel<<<149, 1024>>>(t_w2, f_w2, t_w1, f_w1);

    dim3 g1(98, BATCH);
    conv1_mma_kernel<<<g1, 256, SMEM1_BYTES>>>(x, t_b1, f_b1);

    dim3 g2(NT2, 2 * BATCH);
    conv2_mma_kernel<<<g2, 256, SMEM2_BYTES>>>(t_b2, f_b2);

    head_kernel<<<BATCH, 128>>>(t_wf, t_bf, f_wf, f_bf, out);
    finalize_kernel<<<1, BATCH>>>(out, out_size);
}